// round 11
// baseline (speedup 1.0000x reference)
#include <cuda_runtime.h>
#include <cuda_bf16.h>
#include <cuda_fp16.h>
#include <cstdint>

#define D_MODEL  1024
#define N_HEADS  16
#define HEAD_DIM 64
#define BATCH    2
#define SEQ      2048
#define M_TOT    (BATCH * SEQ)   // 4096
#define WSZ      (D_MODEL * D_MODEL)

// ---------------- scratch (all splits hold fp16 bits) ----------------
__device__ __align__(1024) __nv_bfloat16 g_qhi[M_TOT * D_MODEL];
__device__ __align__(1024) __nv_bfloat16 g_qlo[M_TOT * D_MODEL];
__device__ __align__(1024) __nv_bfloat16 g_khi[M_TOT * D_MODEL];
__device__ __align__(1024) __nv_bfloat16 g_klo[M_TOT * D_MODEL];
__device__ __align__(1024) __nv_bfloat16 g_vhi[M_TOT * D_MODEL];
__device__ __align__(1024) __nv_bfloat16 g_vlo[M_TOT * D_MODEL];
__device__ __align__(1024) __nv_bfloat16 g_yhi[M_TOT * D_MODEL];
__device__ __align__(1024) __nv_bfloat16 g_ylo[M_TOT * D_MODEL];
__device__ __align__(1024) __nv_bfloat16 g_xhi[M_TOT * D_MODEL];
__device__ __align__(1024) __nv_bfloat16 g_xlo[M_TOT * D_MODEL];
__device__ __align__(1024) __nv_bfloat16 g_whi[4u * WSZ];
__device__ __align__(1024) __nv_bfloat16 g_wlo[4u * WSZ];

// ---------------- helpers ----------------
__device__ __forceinline__ uint32_t smem_u32(const void* p) {
    uint32_t a;
    asm("{ .reg .u64 t; cvta.to.shared.u64 t, %1; cvt.u32.u64 %0, t; }" : "=r"(a) : "l"(p));
    return a;
}
__device__ __forceinline__ uint32_t swz128(uint32_t off) { return off ^ ((off >> 3) & 0x70); }
__device__ __forceinline__ uint32_t swz64(uint32_t off)  { return off ^ ((off >> 3) & 0x30); }
__device__ __forceinline__ void cp16(uint32_t s, const void* g) {
    asm volatile("cp.async.cg.shared.global [%0], [%1], 16;" :: "r"(s), "l"(g));
}
#define CP_COMMIT() asm volatile("cp.async.commit_group;" ::: "memory")
#define CP_WAIT(n)  asm volatile("cp.async.wait_group %0;" :: "n"(n) : "memory")

__device__ __forceinline__ void ldsm4(uint32_t r[4], uint32_t addr) {
    asm volatile("ldmatrix.sync.aligned.m8n8.x4.shared.b16 {%0,%1,%2,%3}, [%4];"
                 : "=r"(r[0]), "=r"(r[1]), "=r"(r[2]), "=r"(r[3]) : "r"(addr));
}
__device__ __forceinline__ void ldsm4t(uint32_t r[4], uint32_t addr) {
    asm volatile("ldmatrix.sync.aligned.m8n8.x4.trans.shared.b16 {%0,%1,%2,%3}, [%4];"
                 : "=r"(r[0]), "=r"(r[1]), "=r"(r[2]), "=r"(r[3]) : "r"(addr));
}
__device__ __forceinline__ void mma_f16(float d[4], const uint32_t a[4],
                                        uint32_t b0, uint32_t b1) {
    asm volatile(
        "mma.sync.aligned.m16n8k16.row.col.f32.f16.f16.f32 "
        "{%0,%1,%2,%3}, {%4,%5,%6,%7}, {%8,%9}, {%0,%1,%2,%3};"
        : "+f"(d[0]), "+f"(d[1]), "+f"(d[2]), "+f"(d[3])
        : "r"(a[0]), "r"(a[1]), "r"(a[2]), "r"(a[3]), "r"(b0), "r"(b1));
}
__device__ __forceinline__ uint32_t pack_f16x2(float v0, float v1) {
    __half2 h = __floats2half2_rn(v0, v1);
    return *reinterpret_cast<uint32_t*>(&h);
}
__device__ __forceinline__ void split2h(float v0, float v1, uint32_t& ph, uint32_t& pl) {
    __half h0 = __float2half_rn(v0), h1 = __float2half_rn(v1);
    __half2 hh = __halves2half2(h0, h1);
    ph = *reinterpret_cast<uint32_t*>(&hh);
    __half l0 = __float2half_rn(v0 - __half2float(h0));
    __half l1 = __float2half_rn(v1 - __half2float(h1));
    __half2 ll = __halves2half2(l0, l1);
    pl = *reinterpret_cast<uint32_t*>(&ll);
}

// ---------------- fused split: x + 4 weights (fp16 hi/lo) ----------------
#define XN4 (M_TOT * D_MODEL / 4)
#define WN4 (WSZ / 4)

__global__ __launch_bounds__(256) void split_all(
    const float4* __restrict__ x,
    const float4* __restrict__ wq, const float4* __restrict__ wk,
    const float4* __restrict__ wv, const float4* __restrict__ wp,
    uint32_t* __restrict__ xhi, uint32_t* __restrict__ xlo,
    uint32_t* __restrict__ whi, uint32_t* __restrict__ wlo)
{
    int i = blockIdx.x * 256 + threadIdx.x;
    const float4* src;
    uint32_t *hi, *lo;
    int off;
    if (i < XN4) {
        src = x; off = i; hi = xhi; lo = xlo;
    } else {
        int j = i - XN4;
        int w = j >> 18;
        off = j & (WN4 - 1);
        src = (w == 0) ? wq : (w == 1) ? wk : (w == 2) ? wv : wp;
        hi = whi + (size_t)w * (WSZ / 2);
        lo = wlo + (size_t)w * (WSZ / 2);
    }
    float4 v = src[off];
    uint32_t h0, l0, h1, l1;
    split2h(v.x, v.y, h0, l0);
    split2h(v.z, v.w, h1, l1);
    hi[2 * off + 0] = h0;
    hi[2 * off + 1] = h1;
    lo[2 * off + 0] = l0;
    lo[2 * off + 1] = l1;
}

// ---------------- HMMA fp16 GEMM (BK=32, SW64, 3-stage) ----------------
// MODE 0 (out-proj): stage {Ah,Al,Bh,Bl}, 3 products, fp32 out (~2^-19 err).
// MODE 1 (QKV):      stage {Ah,Bh,Bl},   2 products (C = Ah*(Bh+Bl), ~2^-11),
//                    fp16 hi/lo split outputs for attention.
#define T_B    8192
#define NSTG   3
#define KCHUNKS (D_MODEL / 32)        // 32

template <int NT>
__device__ __forceinline__ void load_stage(
    uint32_t sbase, const __nv_bfloat16* const* gs, int kc, int tid)
{
    #pragma unroll
    for (int t = 0; t < NT; t++) {
        uint32_t tb = sbase + t * T_B;
        const __nv_bfloat16* g = gs[t] + kc * 32;
        #pragma unroll
        for (int i = 0; i < 2; i++) {
            int u = i * 256 + tid;
            int r = u >> 2, c4 = u & 3;
            cp16(tb + swz64(r * 64 + c4 * 16), g + (size_t)r * D_MODEL + c4 * 8);
        }
    }
}

template <int MODE>
__global__ __launch_bounds__(256, 2) void gemm_hmma(
    const __nv_bfloat16* __restrict__ Ahi, const __nv_bfloat16* __restrict__ Alo,
    const __nv_bfloat16* __restrict__ Whi, const __nv_bfloat16* __restrict__ Wlo,
    const float* __restrict__ biasQ, const float* __restrict__ biasK,
    const float* __restrict__ biasV,
    float* __restrict__ C,
    __nv_bfloat16* __restrict__ QH, __nv_bfloat16* __restrict__ QL,
    __nv_bfloat16* __restrict__ KH, __nv_bfloat16* __restrict__ KL,
    __nv_bfloat16* __restrict__ VH, __nv_bfloat16* __restrict__ VL)
{
    constexpr int NT = (MODE == 0) ? 4 : 3;
    constexpr int STG = NT * T_B;

    extern __shared__ __align__(1024) char smem[];
    const uint32_t sb = smem_u32(smem);
    const int tid = threadIdx.x;
    const int wid = tid >> 5, lane = tid & 31;
    const int which = blockIdx.x >> 3;
    const int n0 = (blockIdx.x & 7) * 128;
    const int m0 = blockIdx.y * 128;
    const int wm = (wid >> 1) * 32;
    const int wn = (wid & 1) * 64;
    const int gid = lane >> 2, tig = lane & 3;

    const float* bias = (which == 0) ? biasQ : (which == 1) ? biasK : biasV;
    __nv_bfloat16* Chi = (which == 0) ? QH : (which == 1) ? KH : VH;
    __nv_bfloat16* Clo = (which == 0) ? QL : (which == 1) ? KL : VL;

    const __nv_bfloat16* a0 = Ahi + (size_t)m0 * D_MODEL;
    const __nv_bfloat16* a1 = Alo + (size_t)m0 * D_MODEL;
    const __nv_bfloat16* b0 = Whi + (size_t)which * WSZ + (size_t)n0 * D_MODEL;
    const __nv_bfloat16* b1 = Wlo + (size_t)which * WSZ + (size_t)n0 * D_MODEL;

    const __nv_bfloat16* gs4[4] = {a0, a1, b0, b1};
    const __nv_bfloat16* gs3[3] = {a0, b0, b1};
    const __nv_bfloat16* const* gs = (MODE == 0) ? gs4 : gs3;
    const int bt = (MODE == 0) ? 2 : 1;     // index of Bh tile within stage

    const int a_row  = wm + (lane & 15);
    const int a_byte = ((lane >> 4) & 1) * 16;
    const int b_row  = wn + ((lane >> 4) & 1) * 8 + (lane & 7);
    const int b_byte = ((lane >> 3) & 1) * 16;

    float d[2][8][4];
    #pragma unroll
    for (int i = 0; i < 2; i++)
        #pragma unroll
        for (int j = 0; j < 8; j++)
            #pragma unroll
            for (int c = 0; c < 4; c++) d[i][j][c] = 0.0f;

    load_stage<NT>(sb + 0 * STG, gs, 0, tid);
    CP_COMMIT();
    load_stage<NT>(sb + 1 * STG, gs, 1, tid);
    CP_COMMIT();

    for (int kc = 0; kc < KCHUNKS; kc++) {
        if (kc + 1 < KCHUNKS) { CP_WAIT(1); } else { CP_WAIT(0); }
        __syncthreads();
        if (kc + 2 < KCHUNKS) {
            load_stage<NT>(sb + ((kc + 2) % NSTG) * STG, gs, kc + 2, tid);
            CP_COMMIT();
        }
        const uint32_t st = sb + (kc % NSTG) * STG;

        #pragma unroll
        for (int ks = 0; ks < 2; ks++) {
            uint32_t ah[2][4], al[2][4];
            #pragma unroll
            for (int am = 0; am < 2; am++) {
                uint32_t off = swz64((uint32_t)(a_row + am * 16) * 64 + a_byte + ks * 32);
                ldsm4(ah[am], st + off);
                if (MODE == 0) ldsm4(al[am], st + T_B + off);
            }
            uint32_t bh[8][2], bl[8][2];
            #pragma unroll
            for (int pr = 0; pr < 4; pr++) {
                uint32_t off = swz64((uint32_t)(b_row + pr * 16) * 64 + b_byte + ks * 32);
                uint32_t r[4];
                ldsm4(r, st + bt * T_B + off);
                bh[2 * pr][0] = r[0]; bh[2 * pr][1] = r[1];
                bh[2 * pr + 1][0] = r[2]; bh[2 * pr + 1][1] = r[3];
                ldsm4(r, st + (bt + 1) * T_B + off);
                bl[2 * pr][0] = r[0]; bl[2 * pr][1] = r[1];
                bl[2 * pr + 1][0] = r[2]; bl[2 * pr + 1][1] = r[3];
            }
            #pragma unroll
            for (int am = 0; am < 2; am++)
                #pragma unroll
                for (int bn = 0; bn < 8; bn++) {
                    mma_f16(d[am][bn], ah[am], bh[bn][0], bh[bn][1]);
                    mma_f16(d[am][bn], ah[am], bl[bn][0], bl[bn][1]);
                    if (MODE == 0)
                        mma_f16(d[am][bn], al[am], bh[bn][0], bh[bn][1]);
                }
        }
    }

    #pragma unroll
    for (int am = 0; am < 2; am++) {
        const int row = m0 + wm + am * 16 + gid;
        #pragma unroll
        for (int bn = 0; bn < 8; bn++) {
            const int col = n0 + wn + bn * 8 + tig * 2;
            const float bv0 = __ldg(&bias[col]);
            const float bv1 = __ldg(&bias[col + 1]);
            float v0 = d[am][bn][0] + bv0, v1 = d[am][bn][1] + bv1;
            float v2 = d[am][bn][2] + bv0, v3 = d[am][bn][3] + bv1;
            if (MODE == 1) {
                uint32_t h, l;
                split2h(v0, v1, h, l);
                *(uint32_t*)&Chi[(size_t)row * D_MODEL + col] = h;
                *(uint32_t*)&Clo[(size_t)row * D_MODEL + col] = l;
                split2h(v2, v3, h, l);
                *(uint32_t*)&Chi[(size_t)(row + 8) * D_MODEL + col] = h;
                *(uint32_t*)&Clo[(size_t)(row + 8) * D_MODEL + col] = l;
            } else {
                *(float2*)&C[(size_t)row * D_MODEL + col] = make_float2(v0, v1);
                *(float2*)&C[(size_t)(row + 8) * D_MODEL + col] = make_float2(v2, v3);
            }
        }
    }
}

// ---------------- HMMA flash attention (fp16, LPT, 2-stage) ----------------
#define AQ 128
#define KV_STG 32768
#define ATT_SMEM (2 * AQ * 128 + 2 * KV_STG)   // 98304

__global__ __launch_bounds__(256) void attn_hmma(
    const __nv_bfloat16* __restrict__ Qhi, const __nv_bfloat16* __restrict__ Qlo,
    const __nv_bfloat16* __restrict__ Khi, const __nv_bfloat16* __restrict__ Klo,
    const __nv_bfloat16* __restrict__ Vhi, const __nv_bfloat16* __restrict__ Vlo,
    __nv_bfloat16* __restrict__ Yhi, __nv_bfloat16* __restrict__ Ylo)
{
    extern __shared__ __align__(1024) char smA[];
    const uint32_t sb = smem_u32(smA);
    const int tid = threadIdx.x, wid = tid >> 5, lane = tid & 31;
    const int gid = lane >> 2, tig = lane & 3;
    const int qblk = gridDim.y - 1 - blockIdx.y;   // LPT
    const int bh = blockIdx.x;
    const int b = bh >> 4, h = bh & 15;
    const size_t base = ((size_t)b * SEQ) * D_MODEL + (size_t)h * HEAD_DIM;

    const uint32_t sQh = sb;
    const uint32_t sQl = sb + AQ * 128;
    const uint32_t sKV = sb + 2 * AQ * 128;

    {
        const __nv_bfloat16* q0 = Qhi + base + (size_t)qblk * AQ * D_MODEL;
        const __nv_bfloat16* q1 = Qlo + base + (size_t)qblk * AQ * D_MODEL;
        #pragma unroll
        for (int i = 0; i < 4; i++) {
            int u = i * 256 + tid;
            int r = u >> 3, c = u & 7;
            cp16(sQh + swz128(r * 128 + c * 16), q0 + (size_t)r * D_MODEL + c * 8);
            cp16(sQl + swz128(r * 128 + c * 16), q1 + (size_t)r * D_MODEL + c * 8);
        }
    }
    CP_COMMIT();

    const int nkt = 2 * qblk + 2;

    {
        const __nv_bfloat16* srcs[4] = {Khi + base, Klo + base, Vhi + base, Vlo + base};
        #pragma unroll
        for (int t = 0; t < 4; t++)
            #pragma unroll
            for (int i = 0; i < 2; i++) {
                int u = i * 256 + tid;
                int r = u >> 3, c = u & 7;
                cp16(sKV + t * 8192 + swz128(r * 128 + c * 16),
                     srcs[t] + (size_t)r * D_MODEL + c * 8);
            }
    }
    CP_COMMIT();
    CP_WAIT(1);
    __syncthreads();

    uint32_t qh[4][4], ql[4][4];
    {
        const int ar = wid * 16 + (lane & 15);
        const int ab = ((lane >> 4) & 1) * 16;
        #pragma unroll
        for (int ks = 0; ks < 4; ks++) {
            ldsm4(qh[ks], sQh + swz128((uint32_t)ar * 128 + ab + ks * 32));
            ldsm4(ql[ks], sQl + swz128((uint32_t)ar * 128 + ab + ks * 32));
        }
    }

    float o[8][4];
    #pragma unroll
    for (int nt = 0; nt < 8; nt++)
        #pragma unroll
        for (int j = 0; j < 4; j++) o[nt][j] = 0.0f;
    float m0 = -1e30f, m1 = -1e30f, l0 = 0.0f, l1 = 0.0f;

    const int qr0 = qblk * AQ + wid * 16 + gid;
    const int row_min = qblk * AQ + wid * 16;
    const int row_max = row_min + 15;

    const int sbr = ((lane >> 4) & 1) * 8 + (lane & 7);
    const int sbb = ((lane >> 3) & 1) * 16;
    const int vrr = lane & 15;
    const int vbb = ((lane >> 4) & 1) * 16;

    const float SC = 0.125f * 1.44269504f;

    for (int kt = 0; kt < nkt; kt++) {
        const uint32_t st = sKV + (uint32_t)(kt & 1) * KV_STG;
        __syncthreads();
        if (kt + 1 < nkt) {
            const size_t koff = base + (size_t)(kt + 1) * 64 * D_MODEL;
            const __nv_bfloat16* srcs[4] = {Khi + koff, Klo + koff, Vhi + koff, Vlo + koff};
            const uint32_t dst = sKV + (uint32_t)((kt + 1) & 1) * KV_STG;
            #pragma unroll
            for (int t = 0; t < 4; t++)
                #pragma unroll
                for (int i = 0; i < 2; i++) {
                    int u = i * 256 + tid;
                    int r = u >> 3, c = u & 7;
                    cp16(dst + t * 8192 + swz128(r * 128 + c * 16),
                         srcs[t] + (size_t)r * D_MODEL + c * 8);
                }
            CP_COMMIT();
            CP_WAIT(1);
        } else {
            CP_WAIT(0);
        }
        __syncthreads();

        if (kt * 64 > row_max) continue;

        float s[8][4];
        #pragma unroll
        for (int nt = 0; nt < 8; nt++)
            #pragma unroll
            for (int j = 0; j < 4; j++) s[nt][j] = 0.0f;

        #pragma unroll
        for (int ks = 0; ks < 4; ks++) {
            #pragma unroll
            for (int np = 0; np < 4; np++) {
                uint32_t off = swz128((uint32_t)(np * 16 + sbr) * 128 + sbb + ks * 32);
                uint32_t rh[4], rl[4];
                ldsm4(rh, st + off);
                ldsm4(rl, st + 8192 + off);
                mma_f16(s[2 * np],     qh[ks], rh[0], rh[1]);
                mma_f16(s[2 * np],     qh[ks], rl[0], rl[1]);
                mma_f16(s[2 * np],     ql[ks], rh[0], rh[1]);
                mma_f16(s[2 * np + 1], qh[ks], rh[2], rh[3]);
                mma_f16(s[2 * np + 1], qh[ks], rl[2], rl[3]);
                mma_f16(s[2 * np + 1], ql[ks], rh[2], rh[3]);
            }
        }

        const bool need_mask = (kt * 64 + 63 > row_min);
        #pragma unroll
        for (int nt = 0; nt < 8; nt++) {
            #pragma unroll
            for (int j = 0; j < 4; j++) s[nt][j] *= SC;
            if (need_mask) {
                const int kc = kt * 64 + nt * 8 + 2 * tig;
                if (kc     > qr0)     s[nt][0] = -1e30f;
                if (kc + 1 > qr0)     s[nt][1] = -1e30f;
                if (kc     > qr0 + 8) s[nt][2] = -1e30f;
                if (kc + 1 > qr0 + 8) s[nt][3] = -1e30f;
            }
        }

        float mx0 = -1e30f, mx1 = -1e30f;
        #pragma unroll
        for (int nt = 0; nt < 8; nt++) {
            mx0 = fmaxf(mx0, fmaxf(s[nt][0], s[nt][1]));
            mx1 = fmaxf(mx1, fmaxf(s[nt][2], s[nt][3]));
        }
        mx0 = fmaxf(mx0, __shfl_xor_sync(0xffffffffu, mx0, 1));
        mx0 = fmaxf(mx0, __shfl_xor_sync(0xffffffffu, mx0, 2));
        mx1 = fmaxf(mx1, __shfl_xor_sync(0xffffffffu, mx1, 1));
        mx1 = fmaxf(mx1, __shfl_xor_sync(0xffffffffu, mx1, 2));
        const float nm0 = fmaxf(m0, mx0), nm1 = fmaxf(m1, mx1);
        const float c0 = exp2f(m0 - nm0), c1 = exp2f(m1 - nm1);
        m0 = nm0; m1 = nm1;

        uint32_t pA[8], pB[8];
        float la0 = 0.0f, la1 = 0.0f;
        #pragma unroll
        for (int nt = 0; nt < 8; nt++) {
            float p0 = exp2f(s[nt][0] - m0), p1 = exp2f(s[nt][1] - m0);
            float p2 = exp2f(s[nt][2] - m1), p3 = exp2f(s[nt][3] - m1);
            la0 += p0 + p1; la1 += p2 + p3;
            pA[nt] = pack_f16x2(p0, p1);
            pB[nt] = pack_f16x2(p2, p3);
        }
        la0 += __shfl_xor_sync(0xffffffffu, la0, 1);
        la0 += __shfl_xor_sync(0xffffffffu, la0, 2);
        la1 += __shfl_xor_sync(0xffffffffu, la1, 1);
        la1 += __shfl_xor_sync(0xffffffffu, la1, 2);
        l0 = l0 * c0 + la0;
        l1 = l1 * c1 + la1;
        #pragma unroll
        for (int nt = 0; nt < 8; nt++) {
            o[nt][0] *= c0; o[nt][1] *= c0;
            o[nt][2] *= c1; o[nt][3] *= c1;
        }

        #pragma unroll
        for (int kk = 0; kk < 4; kk++) {
            uint32_t aH[4] = {pA[2 * kk], pB[2 * kk], pA[2 * kk + 1], pB[2 * kk + 1]};
            #pragma unroll
            for (int np = 0; np < 4; np++) {
                uint32_t off = swz128((uint32_t)(kk * 16 + vrr) * 128 + vbb + np * 32);
                uint32_t rh[4], rl[4];
                ldsm4t(rh, st + 16384 + off);
                ldsm4t(rl, st + 24576 + off);
                mma_f16(o[2 * np],     aH, rh[0], rh[1]);
                mma_f16(o[2 * np],     aH, rl[0], rl[1]);
                mma_f16(o[2 * np + 1], aH, rh[2], rh[3]);
                mma_f16(o[2 * np + 1], aH, rl[2], rl[3]);
            }
        }
    }

    // epilogue: normalize, fp16 hi/lo split for out-proj
    const float i0 = 1.0f / l0, i1 = 1.0f / l1;
    const size_t r0a = base + (size_t)qr0 * D_MODEL;
    const size_t r1a = base + (size_t)(qr0 + 8) * D_MODEL;
    #pragma unroll
    for (int nt = 0; nt < 8; nt++) {
        const int col = nt * 8 + 2 * tig;
        uint32_t hjk, ljk;
        split2h(o[nt][0] * i0, o[nt][1] * i0, hjk, ljk);
        *(uint32_t*)&Yhi[r0a + col] = hjk;
        *(uint32_t*)&Ylo[r0a + col] = ljk;
        split2h(o[nt][2] * i1, o[nt][3] * i1, hjk, ljk);
        *(uint32_t*)&Yhi[r1a + col] = hjk;
        *(uint32_t*)&Ylo[r1a + col] = ljk;
    }
}

// ---------------- launch ----------------
extern "C" void kernel_launch(void* const* d_in, const int* in_sizes, int n_in,
                              void* d_out, int out_size)
{
    const float* x  = (const float*)d_in[0];
    const float* Wq = (const float*)d_in[1];
    const float* bq = (const float*)d_in[2];
    const float* Wk = (const float*)d_in[3];
    const float* bk = (const float*)d_in[4];
    const float* Wv = (const float*)d_in[5];
    const float* bv = (const float*)d_in[6];
    const float* Wp = (const float*)d_in[7];
    const float* bp = (const float*)d_in[8];
    float* out = (float*)d_out;

    __nv_bfloat16 *qhi, *qlo, *khi, *klo, *vhi, *vlo, *yhi, *ylo, *xhi, *xlo, *whi, *wlo;
    cudaGetSymbolAddress((void**)&qhi, g_qhi);
    cudaGetSymbolAddress((void**)&qlo, g_qlo);
    cudaGetSymbolAddress((void**)&khi, g_khi);
    cudaGetSymbolAddress((void**)&klo, g_klo);
    cudaGetSymbolAddress((void**)&vhi, g_vhi);
    cudaGetSymbolAddress((void**)&vlo, g_vlo);
    cudaGetSymbolAddress((void**)&yhi, g_yhi);
    cudaGetSymbolAddress((void**)&ylo, g_ylo);
    cudaGetSymbolAddress((void**)&xhi, g_xhi);
    cudaGetSymbolAddress((void**)&xlo, g_xlo);
    cudaGetSymbolAddress((void**)&whi, g_whi);
    cudaGetSymbolAddress((void**)&wlo, g_wlo);

    cudaFuncSetAttribute(gemm_hmma<0>,
                         cudaFuncAttributeMaxDynamicSharedMemorySize, NSTG * 4 * T_B);
    cudaFuncSetAttribute(gemm_hmma<1>,
                         cudaFuncAttributeMaxDynamicSharedMemorySize, NSTG * 3 * T_B);
    cudaFuncSetAttribute(attn_hmma,
                         cudaFuncAttributeMaxDynamicSharedMemorySize, ATT_SMEM);

    split_all<<<(XN4 + 4 * WN4) / 256, 256>>>(
        (const float4*)x, (const float4*)Wq, (const float4*)Wk,
        (const float4*)Wv, (const float4*)Wp,
        (uint32_t*)xhi, (uint32_t*)xlo, (uint32_t*)whi, (uint32_t*)wlo);

    gemm_hmma<1><<<dim3(24, 32), 256, NSTG * 3 * T_B>>>(
        xhi, xlo, whi, wlo, bq, bk, bv,
        nullptr, qhi, qlo, khi, klo, vhi, vlo);

    attn_hmma<<<dim3(BATCH * N_HEADS, SEQ / AQ), 256, ATT_SMEM>>>(
        qhi, qlo, khi, klo, vhi, vlo, yhi, ylo);

    gemm_hmma<0><<<dim3(8, 32), 256, NSTG * 4 * T_B>>>(
        yhi, ylo, whi + 3u * WSZ, wlo + 3u * WSZ, bp, nullptr, nullptr,
        out, nullptr, nullptr, nullptr, nullptr, nullptr, nullptr);
}

// round 12
// speedup vs baseline: 1.5372x; 1.5372x over previous
#include <cuda_runtime.h>
#include <cuda_bf16.h>
#include <cuda_fp16.h>
#include <cstdint>

#define D_MODEL  1024
#define N_HEADS  16
#define HEAD_DIM 64
#define BATCH    2
#define SEQ      2048
#define M_TOT    (BATCH * SEQ)   // 4096
#define WSZ      (D_MODEL * D_MODEL)

// ---------------- scratch ----------------
// q/k/v hi/lo: fp16 bits. y hi/lo: bf16 bits. x hi: fp16 bits.
// w slots 0..2 (QKV): fp16 bits of 256*w. slot 3 (Wp): bf16 bits.
__device__ __align__(1024) __nv_bfloat16 g_qhi[M_TOT * D_MODEL];
__device__ __align__(1024) __nv_bfloat16 g_qlo[M_TOT * D_MODEL];
__device__ __align__(1024) __nv_bfloat16 g_khi[M_TOT * D_MODEL];
__device__ __align__(1024) __nv_bfloat16 g_klo[M_TOT * D_MODEL];
__device__ __align__(1024) __nv_bfloat16 g_vhi[M_TOT * D_MODEL];
__device__ __align__(1024) __nv_bfloat16 g_vlo[M_TOT * D_MODEL];
__device__ __align__(1024) __nv_bfloat16 g_yhi[M_TOT * D_MODEL];
__device__ __align__(1024) __nv_bfloat16 g_ylo[M_TOT * D_MODEL];
__device__ __align__(1024) __nv_bfloat16 g_xhi[M_TOT * D_MODEL];
__device__ __align__(1024) __nv_bfloat16 g_whi[4u * WSZ];
__device__ __align__(1024) __nv_bfloat16 g_wlo[4u * WSZ];

// ---------------- helpers ----------------
__device__ __forceinline__ uint32_t smem_u32(const void* p) {
    uint32_t a;
    asm("{ .reg .u64 t; cvta.to.shared.u64 t, %1; cvt.u32.u64 %0, t; }" : "=r"(a) : "l"(p));
    return a;
}
__device__ __forceinline__ uint32_t swz128(uint32_t off) { return off ^ ((off >> 3) & 0x70); }
__device__ __forceinline__ uint32_t swz64(uint32_t off)  { return off ^ ((off >> 3) & 0x30); }
__device__ __forceinline__ void cp16(uint32_t s, const void* g) {
    asm volatile("cp.async.cg.shared.global [%0], [%1], 16;" :: "r"(s), "l"(g));
}
#define CP_COMMIT() asm volatile("cp.async.commit_group;" ::: "memory")
#define CP_WAIT(n)  asm volatile("cp.async.wait_group %0;" :: "n"(n) : "memory")

__device__ __forceinline__ void ldsm4(uint32_t r[4], uint32_t addr) {
    asm volatile("ldmatrix.sync.aligned.m8n8.x4.shared.b16 {%0,%1,%2,%3}, [%4];"
                 : "=r"(r[0]), "=r"(r[1]), "=r"(r[2]), "=r"(r[3]) : "r"(addr));
}
__device__ __forceinline__ void ldsm4t(uint32_t r[4], uint32_t addr) {
    asm volatile("ldmatrix.sync.aligned.m8n8.x4.trans.shared.b16 {%0,%1,%2,%3}, [%4];"
                 : "=r"(r[0]), "=r"(r[1]), "=r"(r[2]), "=r"(r[3]) : "r"(addr));
}
__device__ __forceinline__ void mma_bf16(float d[4], const uint32_t a[4],
                                         uint32_t b0, uint32_t b1) {
    asm volatile(
        "mma.sync.aligned.m16n8k16.row.col.f32.bf16.bf16.f32 "
        "{%0,%1,%2,%3}, {%4,%5,%6,%7}, {%8,%9}, {%0,%1,%2,%3};"
        : "+f"(d[0]), "+f"(d[1]), "+f"(d[2]), "+f"(d[3])
        : "r"(a[0]), "r"(a[1]), "r"(a[2]), "r"(a[3]), "r"(b0), "r"(b1));
}
__device__ __forceinline__ void mma_f16(float d[4], const uint32_t a[4],
                                        uint32_t b0, uint32_t b1) {
    asm volatile(
        "mma.sync.aligned.m16n8k16.row.col.f32.f16.f16.f32 "
        "{%0,%1,%2,%3}, {%4,%5,%6,%7}, {%8,%9}, {%0,%1,%2,%3};"
        : "+f"(d[0]), "+f"(d[1]), "+f"(d[2]), "+f"(d[3])
        : "r"(a[0]), "r"(a[1]), "r"(a[2]), "r"(a[3]), "r"(b0), "r"(b1));
}
__device__ __forceinline__ uint32_t pack_bf16x2(float lo, float hi) {
    uint32_t r;
    asm("cvt.rn.bf16x2.f32 %0, %1, %2;" : "=r"(r) : "f"(hi), "f"(lo));
    return r;
}
__device__ __forceinline__ void split2(float v0, float v1, uint32_t& ph, uint32_t& pl) {
    ph = pack_bf16x2(v0, v1);
    float r0 = __uint_as_float(ph << 16);
    float r1 = __uint_as_float(ph & 0xffff0000u);
    pl = pack_bf16x2(v0 - r0, v1 - r1);
}
__device__ __forceinline__ uint32_t pack_f16x2(float v0, float v1) {
    __half2 h = __floats2half2_rn(v0, v1);
    return *reinterpret_cast<uint32_t*>(&h);
}
__device__ __forceinline__ void split2h(float v0, float v1, uint32_t& ph, uint32_t& pl) {
    __half h0 = __float2half_rn(v0), h1 = __float2half_rn(v1);
    __half2 hh = __halves2half2(h0, h1);
    ph = *reinterpret_cast<uint32_t*>(&hh);
    __half l0 = __float2half_rn(v0 - __half2float(h0));
    __half l1 = __float2half_rn(v1 - __half2float(h1));
    __half2 ll = __halves2half2(l0, l1);
    pl = *reinterpret_cast<uint32_t*>(&ll);
}

// ---------------- fused split ----------------
// x -> fp16 hi only. wq/wk/wv -> fp16 hi/lo of 256*w. wp -> bf16 hi/lo.
#define XN4 (M_TOT * D_MODEL / 4)
#define WN4 (WSZ / 4)

__global__ __launch_bounds__(256) void split_all(
    const float4* __restrict__ x,
    const float4* __restrict__ wq, const float4* __restrict__ wk,
    const float4* __restrict__ wv, const float4* __restrict__ wp,
    uint32_t* __restrict__ xhi,
    uint32_t* __restrict__ whi, uint32_t* __restrict__ wlo)
{
    int i = blockIdx.x * 256 + threadIdx.x;
    if (i < XN4) {
        float4 v = x[i];
        xhi[2 * i + 0] = pack_f16x2(v.x, v.y);
        xhi[2 * i + 1] = pack_f16x2(v.z, v.w);
        return;
    }
    int j = i - XN4;
    int w = j >> 18;
    int off = j & (WN4 - 1);
    const float4* src = (w == 0) ? wq : (w == 1) ? wk : (w == 2) ? wv : wp;
    uint32_t* hi = whi + (size_t)w * (WSZ / 2);
    uint32_t* lo = wlo + (size_t)w * (WSZ / 2);
    float4 v = src[off];
    uint32_t h0, l0, h1, l1;
    if (w < 3) {
        // scale by 256 so fp16 lo stays NORMAL (subnormal HMMA slow path!)
        split2h(v.x * 256.0f, v.y * 256.0f, h0, l0);
        split2h(v.z * 256.0f, v.w * 256.0f, h1, l1);
    } else {
        split2(v.x, v.y, h0, l0);
        split2(v.z, v.w, h1, l1);
    }
    hi[2 * off + 0] = h0;
    hi[2 * off + 1] = h1;
    lo[2 * off + 0] = l0;
    lo[2 * off + 1] = l1;
}

// ---------------- HMMA GEMM (BK=32, SW64, 3-stage, 1 sync/chunk) ----------------
// MODE 0 (out-proj): bf16, 4 tiles {Ah,Al,Bh,Bl}, 3 products, fp32 out. (R10 exact)
// MODE 1 (QKV): fp16, 3 tiles {Ah,Bh,Bl}, 2 products, scaled W (x2^8), fp16 split out.
#define T_B    8192
#define NSTG   3
#define KCHUNKS (D_MODEL / 32)        // 32

__device__ __forceinline__ void load_stage4(
    uint32_t sbase, const __nv_bfloat16* a0, const __nv_bfloat16* a1,
    const __nv_bfloat16* b0, const __nv_bfloat16* b1, int kc, int tid)
{
    const __nv_bfloat16* gs[4] = {a0, a1, b0, b1};
    #pragma unroll
    for (int t = 0; t < 4; t++) {
        uint32_t tb = sbase + t * T_B;
        const __nv_bfloat16* g = gs[t] + kc * 32;
        #pragma unroll
        for (int i = 0; i < 2; i++) {
            int u = i * 256 + tid;
            int r = u >> 2, c4 = u & 3;
            cp16(tb + swz64(r * 64 + c4 * 16), g + (size_t)r * D_MODEL + c4 * 8);
        }
    }
}
__device__ __forceinline__ void load_stage3(
    uint32_t sbase, const __nv_bfloat16* a0,
    const __nv_bfloat16* b0, const __nv_bfloat16* b1, int kc, int tid)
{
    const __nv_bfloat16* gs[3] = {a0, b0, b1};
    #pragma unroll
    for (int t = 0; t < 3; t++) {
        uint32_t tb = sbase + t * T_B;
        const __nv_bfloat16* g = gs[t] + kc * 32;
        #pragma unroll
        for (int i = 0; i < 2; i++) {
            int u = i * 256 + tid;
            int r = u >> 2, c4 = u & 3;
            cp16(tb + swz64(r * 64 + c4 * 16), g + (size_t)r * D_MODEL + c4 * 8);
        }
    }
}

template <int MODE>
__global__ __launch_bounds__(256, 2) void gemm_hmma(
    const __nv_bfloat16* __restrict__ Ahi, const __nv_bfloat16* __restrict__ Alo,
    const __nv_bfloat16* __restrict__ Whi, const __nv_bfloat16* __restrict__ Wlo,
    const float* __restrict__ biasQ, const float* __restrict__ biasK,
    const float* __restrict__ biasV,
    float* __restrict__ C,
    __nv_bfloat16* __restrict__ QH, __nv_bfloat16* __restrict__ QL,
    __nv_bfloat16* __restrict__ KH, __nv_bfloat16* __restrict__ KL,
    __nv_bfloat16* __restrict__ VH, __nv_bfloat16* __restrict__ VL)
{
    constexpr int NT = (MODE == 0) ? 4 : 3;
    constexpr int STG = NT * T_B;
    constexpr int BT = (MODE == 0) ? 2 : 1;   // Bh tile index within stage

    extern __shared__ __align__(1024) char smem[];
    const uint32_t sb = smem_u32(smem);
    const int tid = threadIdx.x;
    const int wid = tid >> 5, lane = tid & 31;
    const int which = blockIdx.x >> 3;
    const int n0 = (blockIdx.x & 7) * 128;
    const int m0 = blockIdx.y * 128;
    const int wm = (wid >> 1) * 32;
    const int wn = (wid & 1) * 64;
    const int gid = lane >> 2, tig = lane & 3;

    const float* bias = (which == 0) ? biasQ : (which == 1) ? biasK : biasV;
    __nv_bfloat16* Chi = (which == 0) ? QH : (which == 1) ? KH : VH;
    __nv_bfloat16* Clo = (which == 0) ? QL : (which == 1) ? KL : VL;

    const __nv_bfloat16* a0 = Ahi + (size_t)m0 * D_MODEL;
    const __nv_bfloat16* a1 = (MODE == 0) ? (Alo + (size_t)m0 * D_MODEL) : nullptr;
    const __nv_bfloat16* b0 = Whi + (size_t)which * WSZ + (size_t)n0 * D_MODEL;
    const __nv_bfloat16* b1 = Wlo + (size_t)which * WSZ + (size_t)n0 * D_MODEL;

    const int a_row  = wm + (lane & 15);
    const int a_byte = ((lane >> 4) & 1) * 16;
    const int b_row  = wn + ((lane >> 4) & 1) * 8 + (lane & 7);
    const int b_byte = ((lane >> 3) & 1) * 16;

    float d[2][8][4];
    #pragma unroll
    for (int i = 0; i < 2; i++)
        #pragma unroll
        for (int j = 0; j < 8; j++)
            #pragma unroll
            for (int c = 0; c < 4; c++) d[i][j][c] = 0.0f;

    if (MODE == 0) {
        load_stage4(sb + 0 * STG, a0, a1, b0, b1, 0, tid);
        CP_COMMIT();
        load_stage4(sb + 1 * STG, a0, a1, b0, b1, 1, tid);
        CP_COMMIT();
    } else {
        load_stage3(sb + 0 * STG, a0, b0, b1, 0, tid);
        CP_COMMIT();
        load_stage3(sb + 1 * STG, a0, b0, b1, 1, tid);
        CP_COMMIT();
    }

    for (int kc = 0; kc < KCHUNKS; kc++) {
        if (kc + 1 < KCHUNKS) { CP_WAIT(1); } else { CP_WAIT(0); }
        __syncthreads();
        if (kc + 2 < KCHUNKS) {
            if (MODE == 0)
                load_stage4(sb + ((kc + 2) % NSTG) * STG, a0, a1, b0, b1, kc + 2, tid);
            else
                load_stage3(sb + ((kc + 2) % NSTG) * STG, a0, b0, b1, kc + 2, tid);
            CP_COMMIT();
        }
        const uint32_t st = sb + (kc % NSTG) * STG;

        #pragma unroll
        for (int ks = 0; ks < 2; ks++) {
            uint32_t ah[2][4], al[2][4];
            #pragma unroll
            for (int am = 0; am < 2; am++) {
                uint32_t off = swz64((uint32_t)(a_row + am * 16) * 64 + a_byte + ks * 32);
                ldsm4(ah[am], st + off);
                if (MODE == 0) ldsm4(al[am], st + T_B + off);
            }
            uint32_t bh[8][2], bl[8][2];
            #pragma unroll
            for (int pr = 0; pr < 4; pr++) {
                uint32_t off = swz64((uint32_t)(b_row + pr * 16) * 64 + b_byte + ks * 32);
                uint32_t r[4];
                ldsm4(r, st + BT * T_B + off);
                bh[2 * pr][0] = r[0]; bh[2 * pr][1] = r[1];
                bh[2 * pr + 1][0] = r[2]; bh[2 * pr + 1][1] = r[3];
                ldsm4(r, st + (BT + 1) * T_B + off);
                bl[2 * pr][0] = r[0]; bl[2 * pr][1] = r[1];
                bl[2 * pr + 1][0] = r[2]; bl[2 * pr + 1][1] = r[3];
            }
            #pragma unroll
            for (int am = 0; am < 2; am++)
                #pragma unroll
                for (int bn = 0; bn < 8; bn++) {
                    if (MODE == 0) {
                        mma_bf16(d[am][bn], ah[am], bh[bn][0], bh[bn][1]);
                        mma_bf16(d[am][bn], ah[am], bl[bn][0], bl[bn][1]);
                        mma_bf16(d[am][bn], al[am], bh[bn][0], bh[bn][1]);
                    } else {
                        mma_f16(d[am][bn], ah[am], bh[bn][0], bh[bn][1]);
                        mma_f16(d[am][bn], ah[am], bl[bn][0], bl[bn][1]);
                    }
                }
        }
    }

    const float osc = (MODE == 1) ? (1.0f / 256.0f) : 1.0f;   // undo W scaling
    #pragma unroll
    for (int am = 0; am < 2; am++) {
        const int row = m0 + wm + am * 16 + gid;
        #pragma unroll
        for (int bn = 0; bn < 8; bn++) {
            const int col = n0 + wn + bn * 8 + tig * 2;
            const float bv0 = __ldg(&bias[col]);
            const float bv1 = __ldg(&bias[col + 1]);
            float v0 = d[am][bn][0] * osc + bv0, v1 = d[am][bn][1] * osc + bv1;
            float v2 = d[am][bn][2] * osc + bv0, v3 = d[am][bn][3] * osc + bv1;
            if (MODE == 1) {
                uint32_t h, l;
                split2h(v0, v1, h, l);
                *(uint32_t*)&Chi[(size_t)row * D_MODEL + col] = h;
                *(uint32_t*)&Clo[(size_t)row * D_MODEL + col] = l;
                split2h(v2, v3, h, l);
                *(uint32_t*)&Chi[(size_t)(row + 8) * D_MODEL + col] = h;
                *(uint32_t*)&Clo[(size_t)(row + 8) * D_MODEL + col] = l;
            } else {
                *(float2*)&C[(size_t)row * D_MODEL + col] = make_float2(v0, v1);
                *(float2*)&C[(size_t)(row + 8) * D_MODEL + col] = make_float2(v2, v3);
            }
        }
    }
}

// ---------------- HMMA flash attention (fp16, LPT, 2-stage) — R10 exact ----------------
#define AQ 128
#define KV_STG 32768
#define ATT_SMEM (2 * AQ * 128 + 2 * KV_STG)   // 98304

__global__ __launch_bounds__(256) void attn_hmma(
    const __nv_bfloat16* __restrict__ Qhi, const __nv_bfloat16* __restrict__ Qlo,
    const __nv_bfloat16* __restrict__ Khi, const __nv_bfloat16* __restrict__ Klo,
    const __nv_bfloat16* __restrict__ Vhi, const __nv_bfloat16* __restrict__ Vlo,
    __nv_bfloat16* __restrict__ Yhi, __nv_bfloat16* __restrict__ Ylo)
{
    extern __shared__ __align__(1024) char smA[];
    const uint32_t sb = smem_u32(smA);
    const int tid = threadIdx.x, wid = tid >> 5, lane = tid & 31;
    const int gid = lane >> 2, tig = lane & 3;
    const int qblk = gridDim.y - 1 - blockIdx.y;   // LPT
    const int bh = blockIdx.x;
    const int b = bh >> 4, h = bh & 15;
    const size_t base = ((size_t)b * SEQ) * D_MODEL + (size_t)h * HEAD_DIM;

    const uint32_t sQh = sb;
    const uint32_t sQl = sb + AQ * 128;
    const uint32_t sKV = sb + 2 * AQ * 128;

    {
        const __nv_bfloat16* q0 = Qhi + base + (size_t)qblk * AQ * D_MODEL;
        const __nv_bfloat16* q1 = Qlo + base + (size_t)qblk * AQ * D_MODEL;
        #pragma unroll
        for (int i = 0; i < 4; i++) {
            int u = i * 256 + tid;
            int r = u >> 3, c = u & 7;
            cp16(sQh + swz128(r * 128 + c * 16), q0 + (size_t)r * D_MODEL + c * 8);
            cp16(sQl + swz128(r * 128 + c * 16), q1 + (size_t)r * D_MODEL + c * 8);
        }
    }
    CP_COMMIT();

    const int nkt = 2 * qblk + 2;

    {
        const __nv_bfloat16* srcs[4] = {Khi + base, Klo + base, Vhi + base, Vlo + base};
        #pragma unroll
        for (int t = 0; t < 4; t++)
            #pragma unroll
            for (int i = 0; i < 2; i++) {
                int u = i * 256 + tid;
                int r = u >> 3, c = u & 7;
                cp16(sKV + t * 8192 + swz128(r * 128 + c * 16),
                     srcs[t] + (size_t)r * D_MODEL + c * 8);
            }
    }
    CP_COMMIT();
    CP_WAIT(1);
    __syncthreads();

    uint32_t qh[4][4], ql[4][4];
    {
        const int ar = wid * 16 + (lane & 15);
        const int ab = ((lane >> 4) & 1) * 16;
        #pragma unroll
        for (int ks = 0; ks < 4; ks++) {
            ldsm4(qh[ks], sQh + swz128((uint32_t)ar * 128 + ab + ks * 32));
            ldsm4(ql[ks], sQl + swz128((uint32_t)ar * 128 + ab + ks * 32));
        }
    }

    float o[8][4];
    #pragma unroll
    for (int nt = 0; nt < 8; nt++)
        #pragma unroll
        for (int j = 0; j < 4; j++) o[nt][j] = 0.0f;
    float m0 = -1e30f, m1 = -1e30f, l0 = 0.0f, l1 = 0.0f;

    const int qr0 = qblk * AQ + wid * 16 + gid;
    const int row_min = qblk * AQ + wid * 16;
    const int row_max = row_min + 15;

    const int sbr = ((lane >> 4) & 1) * 8 + (lane & 7);
    const int sbb = ((lane >> 3) & 1) * 16;
    const int vrr = lane & 15;
    const int vbb = ((lane >> 4) & 1) * 16;

    const float SC = 0.125f * 1.44269504f;

    for (int kt = 0; kt < nkt; kt++) {
        const uint32_t st = sKV + (uint32_t)(kt & 1) * KV_STG;
        __syncthreads();
        if (kt + 1 < nkt) {
            const size_t koff = base + (size_t)(kt + 1) * 64 * D_MODEL;
            const __nv_bfloat16* srcs[4] = {Khi + koff, Klo + koff, Vhi + koff, Vlo + koff};
            const uint32_t dst = sKV + (uint32_t)((kt + 1) & 1) * KV_STG;
            #pragma unroll
            for (int t = 0; t < 4; t++)
                #pragma unroll
                for (int i = 0; i < 2; i++) {
                    int u = i * 256 + tid;
                    int r = u >> 3, c = u & 7;
                    cp16(dst + t * 8192 + swz128(r * 128 + c * 16),
                         srcs[t] + (size_t)r * D_MODEL + c * 8);
                }
            CP_COMMIT();
            CP_WAIT(1);
        } else {
            CP_WAIT(0);
        }
        __syncthreads();

        if (kt * 64 > row_max) continue;

        float s[8][4];
        #pragma unroll
        for (int nt = 0; nt < 8; nt++)
            #pragma unroll
            for (int j = 0; j < 4; j++) s[nt][j] = 0.0f;

        #pragma unroll
        for (int ks = 0; ks < 4; ks++) {
            #pragma unroll
            for (int np = 0; np < 4; np++) {
                uint32_t off = swz128((uint32_t)(np * 16 + sbr) * 128 + sbb + ks * 32);
                uint32_t rh[4], rl[4];
                ldsm4(rh, st + off);
                ldsm4(rl, st + 8192 + off);
                mma_f16(s[2 * np],     qh[ks], rh[0], rh[1]);
                mma_f16(s[2 * np],     qh[ks], rl[0], rl[1]);
                mma_f16(s[2 * np],     ql[ks], rh[0], rh[1]);
                mma_f16(s[2 * np + 1], qh[ks], rh[2], rh[3]);
                mma_f16(s[2 * np + 1], qh[ks], rl[2], rl[3]);
                mma_f16(s[2 * np + 1], ql[ks], rh[2], rh[3]);
            }
        }

        const bool need_mask = (kt * 64 + 63 > row_min);
        #pragma unroll
        for (int nt = 0; nt < 8; nt++) {
            #pragma unroll
            for (int j = 0; j < 4; j++) s[nt][j] *= SC;
            if (need_mask) {
                const int kc = kt * 64 + nt * 8 + 2 * tig;
                if (kc     > qr0)     s[nt][0] = -1e30f;
                if (kc + 1 > qr0)     s[nt][1] = -1e30f;
                if (kc     > qr0 + 8) s[nt][2] = -1e30f;
                if (kc + 1 > qr0 + 8) s[nt][3] = -1e30f;
            }
        }

        float mx0 = -1e30f, mx1 = -1e30f;
        #pragma unroll
        for (int nt = 0; nt < 8; nt++) {
            mx0 = fmaxf(mx0, fmaxf(s[nt][0], s[nt][1]));
            mx1 = fmaxf(mx1, fmaxf(s[nt][2], s[nt][3]));
        }
        mx0 = fmaxf(mx0, __shfl_xor_sync(0xffffffffu, mx0, 1));
        mx0 = fmaxf(mx0, __shfl_xor_sync(0xffffffffu, mx0, 2));
        mx1 = fmaxf(mx1, __shfl_xor_sync(0xffffffffu, mx1, 1));
        mx1 = fmaxf(mx1, __shfl_xor_sync(0xffffffffu, mx1, 2));
        const float nm0 = fmaxf(m0, mx0), nm1 = fmaxf(m1, mx1);
        const float c0 = exp2f(m0 - nm0), c1 = exp2f(m1 - nm1);
        m0 = nm0; m1 = nm1;

        uint32_t pA[8], pB[8];
        float la0 = 0.0f, la1 = 0.0f;
        #pragma unroll
        for (int nt = 0; nt < 8; nt++) {
            float p0 = exp2f(s[nt][0] - m0), p1 = exp2f(s[nt][1] - m0);
            float p2 = exp2f(s[nt][2] - m1), p3 = exp2f(s[nt][3] - m1);
            la0 += p0 + p1; la1 += p2 + p3;
            pA[nt] = pack_f16x2(p0, p1);
            pB[nt] = pack_f16x2(p2, p3);
        }
        la0 += __shfl_xor_sync(0xffffffffu, la0, 1);
        la0 += __shfl_xor_sync(0xffffffffu, la0, 2);
        la1 += __shfl_xor_sync(0xffffffffu, la1, 1);
        la1 += __shfl_xor_sync(0xffffffffu, la1, 2);
        l0 = l0 * c0 + la0;
        l1 = l1 * c1 + la1;
        #pragma unroll
        for (int nt = 0; nt < 8; nt++) {
            o[nt][0] *= c0; o[nt][1] *= c0;
            o[nt][2] *= c1; o[nt][3] *= c1;
        }

        #pragma unroll
        for (int kk = 0; kk < 4; kk++) {
            uint32_t aH[4] = {pA[2 * kk], pB[2 * kk], pA[2 * kk + 1], pB[2 * kk + 1]};
            #pragma unroll
            for (int np = 0; np < 4; np++) {
                uint32_t off = swz128((uint32_t)(kk * 16 + vrr) * 128 + vbb + np * 32);
                uint32_t rh[4], rl[4];
                ldsm4t(rh, st + 16384 + off);
                ldsm4t(rl, st + 24576 + off);
                mma_f16(o[2 * np],     aH, rh[0], rh[1]);
                mma_f16(o[2 * np],     aH, rl[0], rl[1]);
                mma_f16(o[2 * np + 1], aH, rh[2], rh[3]);
                mma_f16(o[2 * np + 1], aH, rl[2], rl[3]);
            }
        }
    }

    // epilogue: normalize, bf16 hi/lo split for the bf16 out-proj
    const float i0 = 1.0f / l0, i1 = 1.0f / l1;
    const size_t r0a = base + (size_t)qr0 * D_MODEL;
    const size_t r1a = base + (size_t)(qr0 + 8) * D_MODEL;
    #pragma unroll
    for (int nt = 0; nt < 8; nt++) {
        const int col = nt * 8 + 2 * tig;
        uint32_t hjk, ljk;
        split2(o[nt][0] * i0, o[nt][1] * i0, hjk, ljk);
        *(uint32_t*)&Yhi[r0a + col] = hjk;
        *(uint32_t*)&Ylo[r0a + col] = ljk;
        split2(o[nt][2] * i1, o[nt][3] * i1, hjk, ljk);
        *(uint32_t*)&Yhi[r1a + col] = hjk;
        *(uint32_t*)&Ylo[r1a + col] = ljk;
    }
}

// ---------------- launch ----------------
extern "C" void kernel_launch(void* const* d_in, const int* in_sizes, int n_in,
                              void* d_out, int out_size)
{
    const float* x  = (const float*)d_in[0];
    const float* Wq = (const float*)d_in[1];
    const float* bq = (const float*)d_in[2];
    const float* Wk = (const float*)d_in[3];
    const float* bk = (const float*)d_in[4];
    const float* Wv = (const float*)d_in[5];
    const float* bv = (const float*)d_in[6];
    const float* Wp = (const float*)d_in[7];
    const float* bp = (const float*)d_in[8];
    float* out = (float*)d_out;

    __nv_bfloat16 *qhi, *qlo, *khi, *klo, *vhi, *vlo, *yhi, *ylo, *xhi, *whi, *wlo;
    cudaGetSymbolAddress((void**)&qhi, g_qhi);
    cudaGetSymbolAddress((void**)&qlo, g_qlo);
    cudaGetSymbolAddress((void**)&khi, g_khi);
    cudaGetSymbolAddress((void**)&klo, g_klo);
    cudaGetSymbolAddress((void**)&vhi, g_vhi);
    cudaGetSymbolAddress((void**)&vlo, g_vlo);
    cudaGetSymbolAddress((void**)&yhi, g_yhi);
    cudaGetSymbolAddress((void**)&ylo, g_ylo);
    cudaGetSymbolAddress((void**)&xhi, g_xhi);
    cudaGetSymbolAddress((void**)&whi, g_whi);
    cudaGetSymbolAddress((void**)&wlo, g_wlo);

    cudaFuncSetAttribute(gemm_hmma<0>,
                         cudaFuncAttributeMaxDynamicSharedMemorySize, NSTG * 4 * T_B);
    cudaFuncSetAttribute(gemm_hmma<1>,
                         cudaFuncAttributeMaxDynamicSharedMemorySize, NSTG * 3 * T_B);
    cudaFuncSetAttribute(attn_hmma,
                         cudaFuncAttributeMaxDynamicSharedMemorySize, ATT_SMEM);

    split_all<<<(XN4 + 4 * WN4) / 256, 256>>>(
        (const float4*)x, (const float4*)Wq, (const float4*)Wk,
        (const float4*)Wv, (const float4*)Wp,
        (uint32_t*)xhi, (uint32_t*)whi, (uint32_t*)wlo);

    gemm_hmma<1><<<dim3(24, 32), 256, NSTG * 3 * T_B>>>(
        xhi, nullptr, whi, wlo, bq, bk, bv,
        nullptr, qhi, qlo, khi, klo, vhi, vlo);

    attn_hmma<<<dim3(BATCH * N_HEADS, SEQ / AQ), 256, ATT_SMEM>>>(
        qhi, qlo, khi, klo, vhi, vlo, yhi, ylo);

    gemm_hmma<0><<<dim3(8, 32), 256, NSTG * 4 * T_B>>>(
        yhi, ylo, whi + 3u * WSZ, wlo + 3u * WSZ, bp, nullptr, nullptr,
        out, nullptr, nullptr, nullptr, nullptr, nullptr, nullptr);
}

// round 13
// speedup vs baseline: 1.6075x; 1.0458x over previous
#include <cuda_runtime.h>
#include <cuda_bf16.h>
#include <cuda_fp16.h>
#include <cstdint>

#define D_MODEL  1024
#define N_HEADS  16
#define HEAD_DIM 64
#define BATCH    2
#define SEQ      2048
#define M_TOT    (BATCH * SEQ)   // 4096
#define WSZ      (D_MODEL * D_MODEL)

// ---------------- scratch (all fp16 bits) ----------------
// q/k/v hi/lo: fp16 of 16*val. y: single fp16. x: fp16 hi. w: fp16 of 256*w.
__device__ __align__(1024) __nv_bfloat16 g_qhi[M_TOT * D_MODEL];
__device__ __align__(1024) __nv_bfloat16 g_qlo[M_TOT * D_MODEL];
__device__ __align__(1024) __nv_bfloat16 g_khi[M_TOT * D_MODEL];
__device__ __align__(1024) __nv_bfloat16 g_klo[M_TOT * D_MODEL];
__device__ __align__(1024) __nv_bfloat16 g_vhi[M_TOT * D_MODEL];
__device__ __align__(1024) __nv_bfloat16 g_vlo[M_TOT * D_MODEL];
__device__ __align__(1024) __nv_bfloat16 g_yhi[M_TOT * D_MODEL];
__device__ __align__(1024) __nv_bfloat16 g_xhi[M_TOT * D_MODEL];
__device__ __align__(1024) __nv_bfloat16 g_whi[4u * WSZ];
__device__ __align__(1024) __nv_bfloat16 g_wlo[4u * WSZ];

// ---------------- helpers ----------------
__device__ __forceinline__ uint32_t smem_u32(const void* p) {
    uint32_t a;
    asm("{ .reg .u64 t; cvta.to.shared.u64 t, %1; cvt.u32.u64 %0, t; }" : "=r"(a) : "l"(p));
    return a;
}
__device__ __forceinline__ uint32_t swz128(uint32_t off) { return off ^ ((off >> 3) & 0x70); }
__device__ __forceinline__ uint32_t swz64(uint32_t off)  { return off ^ ((off >> 3) & 0x30); }
__device__ __forceinline__ void cp16(uint32_t s, const void* g) {
    asm volatile("cp.async.cg.shared.global [%0], [%1], 16;" :: "r"(s), "l"(g));
}
#define CP_COMMIT() asm volatile("cp.async.commit_group;" ::: "memory")
#define CP_WAIT(n)  asm volatile("cp.async.wait_group %0;" :: "n"(n) : "memory")

__device__ __forceinline__ void ldsm4(uint32_t r[4], uint32_t addr) {
    asm volatile("ldmatrix.sync.aligned.m8n8.x4.shared.b16 {%0,%1,%2,%3}, [%4];"
                 : "=r"(r[0]), "=r"(r[1]), "=r"(r[2]), "=r"(r[3]) : "r"(addr));
}
__device__ __forceinline__ void ldsm4t(uint32_t r[4], uint32_t addr) {
    asm volatile("ldmatrix.sync.aligned.m8n8.x4.trans.shared.b16 {%0,%1,%2,%3}, [%4];"
                 : "=r"(r[0]), "=r"(r[1]), "=r"(r[2]), "=r"(r[3]) : "r"(addr));
}
__device__ __forceinline__ void mma_f16(float d[4], const uint32_t a[4],
                                        uint32_t b0, uint32_t b1) {
    asm volatile(
        "mma.sync.aligned.m16n8k16.row.col.f32.f16.f16.f32 "
        "{%0,%1,%2,%3}, {%4,%5,%6,%7}, {%8,%9}, {%0,%1,%2,%3};"
        : "+f"(d[0]), "+f"(d[1]), "+f"(d[2]), "+f"(d[3])
        : "r"(a[0]), "r"(a[1]), "r"(a[2]), "r"(a[3]), "r"(b0), "r"(b1));
}
__device__ __forceinline__ uint32_t pack_f16x2(float v0, float v1) {
    __half2 h = __floats2half2_rn(v0, v1);
    return *reinterpret_cast<uint32_t*>(&h);
}
__device__ __forceinline__ void split2h(float v0, float v1, uint32_t& ph, uint32_t& pl) {
    __half h0 = __float2half_rn(v0), h1 = __float2half_rn(v1);
    __half2 hh = __halves2half2(h0, h1);
    ph = *reinterpret_cast<uint32_t*>(&hh);
    __half l0 = __float2half_rn(v0 - __half2float(h0));
    __half l1 = __float2half_rn(v1 - __half2float(h1));
    __half2 ll = __halves2half2(l0, l1);
    pl = *reinterpret_cast<uint32_t*>(&ll);
}

// ---------------- fused split ----------------
// x -> fp16 hi. all weights -> fp16 hi/lo of 256*w (keeps lo NORMAL).
#define XN4 (M_TOT * D_MODEL / 4)
#define WN4 (WSZ / 4)

__global__ __launch_bounds__(256) void split_all(
    const float4* __restrict__ x,
    const float4* __restrict__ wq, const float4* __restrict__ wk,
    const float4* __restrict__ wv, const float4* __restrict__ wp,
    uint32_t* __restrict__ xhi,
    uint32_t* __restrict__ whi, uint32_t* __restrict__ wlo)
{
    int i = blockIdx.x * 256 + threadIdx.x;
    if (i < XN4) {
        float4 v = x[i];
        xhi[2 * i + 0] = pack_f16x2(v.x, v.y);
        xhi[2 * i + 1] = pack_f16x2(v.z, v.w);
        return;
    }
    int j = i - XN4;
    int w = j >> 18;
    int off = j & (WN4 - 1);
    const float4* src = (w == 0) ? wq : (w == 1) ? wk : (w == 2) ? wv : wp;
    uint32_t* hi = whi + (size_t)w * (WSZ / 2);
    uint32_t* lo = wlo + (size_t)w * (WSZ / 2);
    float4 v = src[off];
    uint32_t h0, l0, h1, l1;
    split2h(v.x * 256.0f, v.y * 256.0f, h0, l0);
    split2h(v.z * 256.0f, v.w * 256.0f, h1, l1);
    hi[2 * off + 0] = h0;
    hi[2 * off + 1] = h1;
    lo[2 * off + 0] = l0;
    lo[2 * off + 1] = l1;
}

// ---------------- HMMA fp16 2-product GEMM (BK=32, SW64, 3-stage) ----------------
// C = Ah * (256*Wh + 256*Wl) * 2^-8 + bias
// MODE 1 (QKV): outputs fp16 hi/lo of 16*C. MODE 2 (out-proj): fp32 C.
#define T_B    8192
#define NSTG   3
#define STG    (3 * T_B)
#define GEMM_SMEM (NSTG * STG)        // 73728
#define KCHUNKS (D_MODEL / 32)        // 32

__device__ __forceinline__ void load_stage3(
    uint32_t sbase, const __nv_bfloat16* a0,
    const __nv_bfloat16* b0, const __nv_bfloat16* b1, int kc, int tid)
{
    const __nv_bfloat16* gs[3] = {a0, b0, b1};
    #pragma unroll
    for (int t = 0; t < 3; t++) {
        uint32_t tb = sbase + t * T_B;
        const __nv_bfloat16* g = gs[t] + kc * 32;
        #pragma unroll
        for (int i = 0; i < 2; i++) {
            int u = i * 256 + tid;
            int r = u >> 2, c4 = u & 3;
            cp16(tb + swz64(r * 64 + c4 * 16), g + (size_t)r * D_MODEL + c4 * 8);
        }
    }
}

template <int MODE>
__global__ __launch_bounds__(256, 2) void gemm_hmma(
    const __nv_bfloat16* __restrict__ Ahi,
    const __nv_bfloat16* __restrict__ Whi, const __nv_bfloat16* __restrict__ Wlo,
    const float* __restrict__ biasQ, const float* __restrict__ biasK,
    const float* __restrict__ biasV,
    float* __restrict__ C,
    __nv_bfloat16* __restrict__ QH, __nv_bfloat16* __restrict__ QL,
    __nv_bfloat16* __restrict__ KH, __nv_bfloat16* __restrict__ KL,
    __nv_bfloat16* __restrict__ VH, __nv_bfloat16* __restrict__ VL)
{
    extern __shared__ __align__(1024) char smem[];
    const uint32_t sb = smem_u32(smem);
    const int tid = threadIdx.x;
    const int wid = tid >> 5, lane = tid & 31;
    const int which = blockIdx.x >> 3;
    const int n0 = (blockIdx.x & 7) * 128;
    const int m0 = blockIdx.y * 128;
    const int wm = (wid >> 1) * 32;
    const int wn = (wid & 1) * 64;
    const int gid = lane >> 2, tig = lane & 3;

    const float* bias = (which == 0) ? biasQ : (which == 1) ? biasK : biasV;
    __nv_bfloat16* Chi = (which == 0) ? QH : (which == 1) ? KH : VH;
    __nv_bfloat16* Clo = (which == 0) ? QL : (which == 1) ? KL : VL;

    const __nv_bfloat16* a0 = Ahi + (size_t)m0 * D_MODEL;
    const __nv_bfloat16* b0 = Whi + (size_t)which * WSZ + (size_t)n0 * D_MODEL;
    const __nv_bfloat16* b1 = Wlo + (size_t)which * WSZ + (size_t)n0 * D_MODEL;

    const int a_row  = wm + (lane & 15);
    const int a_byte = ((lane >> 4) & 1) * 16;
    const int b_row  = wn + ((lane >> 4) & 1) * 8 + (lane & 7);
    const int b_byte = ((lane >> 3) & 1) * 16;

    float d[2][8][4];
    #pragma unroll
    for (int i = 0; i < 2; i++)
        #pragma unroll
        for (int j = 0; j < 8; j++)
            #pragma unroll
            for (int c = 0; c < 4; c++) d[i][j][c] = 0.0f;

    load_stage3(sb + 0 * STG, a0, b0, b1, 0, tid);
    CP_COMMIT();
    load_stage3(sb + 1 * STG, a0, b0, b1, 1, tid);
    CP_COMMIT();

    for (int kc = 0; kc < KCHUNKS; kc++) {
        if (kc + 1 < KCHUNKS) { CP_WAIT(1); } else { CP_WAIT(0); }
        __syncthreads();
        if (kc + 2 < KCHUNKS) {
            load_stage3(sb + ((kc + 2) % NSTG) * STG, a0, b0, b1, kc + 2, tid);
            CP_COMMIT();
        }
        const uint32_t st = sb + (kc % NSTG) * STG;

        #pragma unroll
        for (int ks = 0; ks < 2; ks++) {
            uint32_t ah[2][4];
            #pragma unroll
            for (int am = 0; am < 2; am++) {
                uint32_t off = swz64((uint32_t)(a_row + am * 16) * 64 + a_byte + ks * 32);
                ldsm4(ah[am], st + off);
            }
            uint32_t bh[8][2], bl[8][2];
            #pragma unroll
            for (int pr = 0; pr < 4; pr++) {
                uint32_t off = swz64((uint32_t)(b_row + pr * 16) * 64 + b_byte + ks * 32);
                uint32_t r[4];
                ldsm4(r, st + 1 * T_B + off);
                bh[2 * pr][0] = r[0]; bh[2 * pr][1] = r[1];
                bh[2 * pr + 1][0] = r[2]; bh[2 * pr + 1][1] = r[3];
                ldsm4(r, st + 2 * T_B + off);
                bl[2 * pr][0] = r[0]; bl[2 * pr][1] = r[1];
                bl[2 * pr + 1][0] = r[2]; bl[2 * pr + 1][1] = r[3];
            }
            #pragma unroll
            for (int am = 0; am < 2; am++)
                #pragma unroll
                for (int bn = 0; bn < 8; bn++) {
                    mma_f16(d[am][bn], ah[am], bh[bn][0], bh[bn][1]);
                    mma_f16(d[am][bn], ah[am], bl[bn][0], bl[bn][1]);
                }
        }
    }

    const float osc = 1.0f / 256.0f;     // undo W scaling
    #pragma unroll
    for (int am = 0; am < 2; am++) {
        const int row = m0 + wm + am * 16 + gid;
        #pragma unroll
        for (int bn = 0; bn < 8; bn++) {
            const int col = n0 + wn + bn * 8 + tig * 2;
            const float bv0 = __ldg(&bias[col]);
            const float bv1 = __ldg(&bias[col + 1]);
            float v0 = d[am][bn][0] * osc + bv0, v1 = d[am][bn][1] * osc + bv1;
            float v2 = d[am][bn][2] * osc + bv0, v3 = d[am][bn][3] * osc + bv1;
            if (MODE == 1) {
                // store 16*val as fp16 hi/lo (lo fully normal)
                uint32_t h, l;
                split2h(v0 * 16.0f, v1 * 16.0f, h, l);
                *(uint32_t*)&Chi[(size_t)row * D_MODEL + col] = h;
                *(uint32_t*)&Clo[(size_t)row * D_MODEL + col] = l;
                split2h(v2 * 16.0f, v3 * 16.0f, h, l);
                *(uint32_t*)&Chi[(size_t)(row + 8) * D_MODEL + col] = h;
                *(uint32_t*)&Clo[(size_t)(row + 8) * D_MODEL + col] = l;
            } else {
                *(float2*)&C[(size_t)row * D_MODEL + col] = make_float2(v0, v1);
                *(float2*)&C[(size_t)(row + 8) * D_MODEL + col] = make_float2(v2, v3);
            }
        }
    }
}

// ---------------- HMMA flash attention (fp16, LPT, 2-stage) ----------------
// Inputs hold 16*q etc: s_acc = 256*(q.k); SC folds in 2^-8.
// O accumulates p*(16v); epilogue divides by 16*l. y written as single fp16.
#define AQ 128
#define KV_STG 32768
#define ATT_SMEM (2 * AQ * 128 + 2 * KV_STG)   // 98304

__global__ __launch_bounds__(256) void attn_hmma(
    const __nv_bfloat16* __restrict__ Qhi, const __nv_bfloat16* __restrict__ Qlo,
    const __nv_bfloat16* __restrict__ Khi, const __nv_bfloat16* __restrict__ Klo,
    const __nv_bfloat16* __restrict__ Vhi, const __nv_bfloat16* __restrict__ Vlo,
    __nv_bfloat16* __restrict__ Yhi)
{
    extern __shared__ __align__(1024) char smA[];
    const uint32_t sb = smem_u32(smA);
    const int tid = threadIdx.x, wid = tid >> 5, lane = tid & 31;
    const int gid = lane >> 2, tig = lane & 3;
    const int qblk = gridDim.y - 1 - blockIdx.y;   // LPT
    const int bh = blockIdx.x;
    const int b = bh >> 4, h = bh & 15;
    const size_t base = ((size_t)b * SEQ) * D_MODEL + (size_t)h * HEAD_DIM;

    const uint32_t sQh = sb;
    const uint32_t sQl = sb + AQ * 128;
    const uint32_t sKV = sb + 2 * AQ * 128;

    {
        const __nv_bfloat16* q0 = Qhi + base + (size_t)qblk * AQ * D_MODEL;
        const __nv_bfloat16* q1 = Qlo + base + (size_t)qblk * AQ * D_MODEL;
        #pragma unroll
        for (int i = 0; i < 4; i++) {
            int u = i * 256 + tid;
            int r = u >> 3, c = u & 7;
            cp16(sQh + swz128(r * 128 + c * 16), q0 + (size_t)r * D_MODEL + c * 8);
            cp16(sQl + swz128(r * 128 + c * 16), q1 + (size_t)r * D_MODEL + c * 8);
        }
    }
    CP_COMMIT();

    const int nkt = 2 * qblk + 2;

    {
        const __nv_bfloat16* srcs[4] = {Khi + base, Klo + base, Vhi + base, Vlo + base};
        #pragma unroll
        for (int t = 0; t < 4; t++)
            #pragma unroll
            for (int i = 0; i < 2; i++) {
                int u = i * 256 + tid;
                int r = u >> 3, c = u & 7;
                cp16(sKV + t * 8192 + swz128(r * 128 + c * 16),
                     srcs[t] + (size_t)r * D_MODEL + c * 8);
            }
    }
    CP_COMMIT();
    CP_WAIT(1);
    __syncthreads();

    uint32_t qh[4][4], ql[4][4];
    {
        const int ar = wid * 16 + (lane & 15);
        const int ab = ((lane >> 4) & 1) * 16;
        #pragma unroll
        for (int ks = 0; ks < 4; ks++) {
            ldsm4(qh[ks], sQh + swz128((uint32_t)ar * 128 + ab + ks * 32));
            ldsm4(ql[ks], sQl + swz128((uint32_t)ar * 128 + ab + ks * 32));
        }
    }

    float o[8][4];
    #pragma unroll
    for (int nt = 0; nt < 8; nt++)
        #pragma unroll
        for (int j = 0; j < 4; j++) o[nt][j] = 0.0f;
    float m0 = -1e30f, m1 = -1e30f, l0 = 0.0f, l1 = 0.0f;

    const int qr0 = qblk * AQ + wid * 16 + gid;
    const int row_min = qblk * AQ + wid * 16;
    const int row_max = row_min + 15;

    const int sbr = ((lane >> 4) & 1) * 8 + (lane & 7);
    const int sbb = ((lane >> 3) & 1) * 16;
    const int vrr = lane & 15;
    const int vbb = ((lane >> 4) & 1) * 16;

    const float SC = 0.125f * 1.44269504f / 256.0f;   // 16q*16k = 256*qk

    for (int kt = 0; kt < nkt; kt++) {
        const uint32_t st = sKV + (uint32_t)(kt & 1) * KV_STG;
        __syncthreads();
        if (kt + 1 < nkt) {
            const size_t koff = base + (size_t)(kt + 1) * 64 * D_MODEL;
            const __nv_bfloat16* srcs[4] = {Khi + koff, Klo + koff, Vhi + koff, Vlo + koff};
            const uint32_t dst = sKV + (uint32_t)((kt + 1) & 1) * KV_STG;
            #pragma unroll
            for (int t = 0; t < 4; t++)
                #pragma unroll
                for (int i = 0; i < 2; i++) {
                    int u = i * 256 + tid;
                    int r = u >> 3, c = u & 7;
                    cp16(dst + t * 8192 + swz128(r * 128 + c * 16),
                         srcs[t] + (size_t)r * D_MODEL + c * 8);
                }
            CP_COMMIT();
            CP_WAIT(1);
        } else {
            CP_WAIT(0);
        }
        __syncthreads();

        if (kt * 64 > row_max) continue;

        float s[8][4];
        #pragma unroll
        for (int nt = 0; nt < 8; nt++)
            #pragma unroll
            for (int j = 0; j < 4; j++) s[nt][j] = 0.0f;

        #pragma unroll
        for (int ks = 0; ks < 4; ks++) {
            #pragma unroll
            for (int np = 0; np < 4; np++) {
                uint32_t off = swz128((uint32_t)(np * 16 + sbr) * 128 + sbb + ks * 32);
                uint32_t rh[4], rl[4];
                ldsm4(rh, st + off);
                ldsm4(rl, st + 8192 + off);
                mma_f16(s[2 * np],     qh[ks], rh[0], rh[1]);
                mma_f16(s[2 * np],     qh[ks], rl[0], rl[1]);
                mma_f16(s[2 * np],     ql[ks], rh[0], rh[1]);
                mma_f16(s[2 * np + 1], qh[ks], rh[2], rh[3]);
                mma_f16(s[2 * np + 1], qh[ks], rl[2], rl[3]);
                mma_f16(s[2 * np + 1], ql[ks], rh[2], rh[3]);
            }
        }

        const bool need_mask = (kt * 64 + 63 > row_min);
        #pragma unroll
        for (int nt = 0; nt < 8; nt++) {
            #pragma unroll
            for (int j = 0; j < 4; j++) s[nt][j] *= SC;
            if (need_mask) {
                const int kc = kt * 64 + nt * 8 + 2 * tig;
                if (kc     > qr0)     s[nt][0] = -1e30f;
                if (kc + 1 > qr0)     s[nt][1] = -1e30f;
                if (kc     > qr0 + 8) s[nt][2] = -1e30f;
                if (kc + 1 > qr0 + 8) s[nt][3] = -1e30f;
            }
        }

        float mx0 = -1e30f, mx1 = -1e30f;
        #pragma unroll
        for (int nt = 0; nt < 8; nt++) {
            mx0 = fmaxf(mx0, fmaxf(s[nt][0], s[nt][1]));
            mx1 = fmaxf(mx1, fmaxf(s[nt][2], s[nt][3]));
        }
        mx0 = fmaxf(mx0, __shfl_xor_sync(0xffffffffu, mx0, 1));
        mx0 = fmaxf(mx0, __shfl_xor_sync(0xffffffffu, mx0, 2));
        mx1 = fmaxf(mx1, __shfl_xor_sync(0xffffffffu, mx1, 1));
        mx1 = fmaxf(mx1, __shfl_xor_sync(0xffffffffu, mx1, 2));
        const float nm0 = fmaxf(m0, mx0), nm1 = fmaxf(m1, mx1);
        const float c0 = exp2f(m0 - nm0), c1 = exp2f(m1 - nm1);
        m0 = nm0; m1 = nm1;

        uint32_t pA[8], pB[8];
        float la0 = 0.0f, la1 = 0.0f;
        #pragma unroll
        for (int nt = 0; nt < 8; nt++) {
            float p0 = exp2f(s[nt][0] - m0), p1 = exp2f(s[nt][1] - m0);
            float p2 = exp2f(s[nt][2] - m1), p3 = exp2f(s[nt][3] - m1);
            la0 += p0 + p1; la1 += p2 + p3;
            pA[nt] = pack_f16x2(p0, p1);
            pB[nt] = pack_f16x2(p2, p3);
        }
        la0 += __shfl_xor_sync(0xffffffffu, la0, 1);
        la0 += __shfl_xor_sync(0xffffffffu, la0, 2);
        la1 += __shfl_xor_sync(0xffffffffu, la1, 1);
        la1 += __shfl_xor_sync(0xffffffffu, la1, 2);
        l0 = l0 * c0 + la0;
        l1 = l1 * c1 + la1;
        #pragma unroll
        for (int nt = 0; nt < 8; nt++) {
            o[nt][0] *= c0; o[nt][1] *= c0;
            o[nt][2] *= c1; o[nt][3] *= c1;
        }

        #pragma unroll
        for (int kk = 0; kk < 4; kk++) {
            uint32_t aH[4] = {pA[2 * kk], pB[2 * kk], pA[2 * kk + 1], pB[2 * kk + 1]};
            #pragma unroll
            for (int np = 0; np < 4; np++) {
                uint32_t off = swz128((uint32_t)(kk * 16 + vrr) * 128 + vbb + np * 32);
                uint32_t rh[4], rl[4];
                ldsm4t(rh, st + 16384 + off);
                ldsm4t(rl, st + 24576 + off);
                mma_f16(o[2 * np],     aH, rh[0], rh[1]);
                mma_f16(o[2 * np],     aH, rl[0], rl[1]);
                mma_f16(o[2 * np + 1], aH, rh[2], rh[3]);
                mma_f16(o[2 * np + 1], aH, rl[2], rl[3]);
            }
        }
    }

    // epilogue: y = o/(16*l), single fp16
    const float i0 = 1.0f / (16.0f * l0), i1 = 1.0f / (16.0f * l1);
    const size_t r0a = base + (size_t)qr0 * D_MODEL;
    const size_t r1a = base + (size_t)(qr0 + 8) * D_MODEL;
    #pragma unroll
    for (int nt = 0; nt < 8; nt++) {
        const int col = nt * 8 + 2 * tig;
        *(uint32_t*)&Yhi[r0a + col] = pack_f16x2(o[nt][0] * i0, o[nt][1] * i0);
        *(uint32_t*)&Yhi[r1a + col] = pack_f16x2(o[nt][2] * i1, o[nt][3] * i1);
    }
}

// ---------------- launch ----------------
extern "C" void kernel_launch(void* const* d_in, const int* in_sizes, int n_in,
                              void* d_out, int out_size)
{
    const float* x  = (const float*)d_in[0];
    const float* Wq = (const float*)d_in[1];
    const float* bq = (const float*)d_in[2];
    const float* Wk = (const float*)d_in[3];
    const float* bk = (const float*)d_in[4];
    const float* Wv = (const float*)d_in[5];
    const float* bv = (const float*)d_in[6];
    const float* Wp = (const float*)d_in[7];
    const float* bp = (const float*)d_in[8];
    float* out = (float*)d_out;

    __nv_bfloat16 *qhi, *qlo, *khi, *klo, *vhi, *vlo, *yhi, *xhi, *whi, *wlo;
    cudaGetSymbolAddress((void**)&qhi, g_qhi);
    cudaGetSymbolAddress((void**)&qlo, g_qlo);
    cudaGetSymbolAddress((void**)&khi, g_khi);
    cudaGetSymbolAddress((void**)&klo, g_klo);
    cudaGetSymbolAddress((void**)&vhi, g_vhi);
    cudaGetSymbolAddress((void**)&vlo, g_vlo);
    cudaGetSymbolAddress((void**)&yhi, g_yhi);
    cudaGetSymbolAddress((void**)&xhi, g_xhi);
    cudaGetSymbolAddress((void**)&whi, g_whi);
    cudaGetSymbolAddress((void**)&wlo, g_wlo);

    cudaFuncSetAttribute(gemm_hmma<1>,
                         cudaFuncAttributeMaxDynamicSharedMemorySize, GEMM_SMEM);
    cudaFuncSetAttribute(gemm_hmma<2>,
                         cudaFuncAttributeMaxDynamicSharedMemorySize, GEMM_SMEM);
    cudaFuncSetAttribute(attn_hmma,
                         cudaFuncAttributeMaxDynamicSharedMemorySize, ATT_SMEM);

    split_all<<<(XN4 + 4 * WN4) / 256, 256>>>(
        (const float4*)x, (const float4*)Wq, (const float4*)Wk,
        (const float4*)Wv, (const float4*)Wp,
        (uint32_t*)xhi, (uint32_t*)whi, (uint32_t*)wlo);

    gemm_hmma<1><<<dim3(24, 32), 256, GEMM_SMEM>>>(
        xhi, whi, wlo, bq, bk, bv,
        nullptr, qhi, qlo, khi, klo, vhi, vlo);

    attn_hmma<<<dim3(BATCH * N_HEADS, SEQ / AQ), 256, ATT_SMEM>>>(
        qhi, qlo, khi, klo, vhi, vlo, yhi);

    gemm_hmma<2><<<dim3(8, 32), 256, GEMM_SMEM>>>(
        yhi, whi + 3u * WSZ, wlo + 3u * WSZ, bp, nullptr, nullptr,
        out, nullptr, nullptr, nullptr, nullptr, nullptr, nullptr);
}

// round 14
// speedup vs baseline: 1.7114x; 1.0646x over previous
#include <cuda_runtime.h>
#include <cuda_bf16.h>
#include <cuda_fp16.h>
#include <cstdint>

#define D_MODEL  1024
#define N_HEADS  16
#define HEAD_DIM 64
#define BATCH    2
#define SEQ      2048
#define M_TOT    (BATCH * SEQ)   // 4096
#define WSZ      (D_MODEL * D_MODEL)

// ---------------- scratch (all fp16 bits) ----------------
// q/k hi/lo: fp16 of 16*val. v: single fp16 of 16*v. y: single fp16.
// x: fp16 hi. w: fp16 hi/lo of 256*w.
__device__ __align__(1024) __nv_bfloat16 g_qhi[M_TOT * D_MODEL];
__device__ __align__(1024) __nv_bfloat16 g_qlo[M_TOT * D_MODEL];
__device__ __align__(1024) __nv_bfloat16 g_khi[M_TOT * D_MODEL];
__device__ __align__(1024) __nv_bfloat16 g_klo[M_TOT * D_MODEL];
__device__ __align__(1024) __nv_bfloat16 g_v16[M_TOT * D_MODEL];
__device__ __align__(1024) __nv_bfloat16 g_yhi[M_TOT * D_MODEL];
__device__ __align__(1024) __nv_bfloat16 g_xhi[M_TOT * D_MODEL];
__device__ __align__(1024) __nv_bfloat16 g_whi[4u * WSZ];
__device__ __align__(1024) __nv_bfloat16 g_wlo[4u * WSZ];

// ---------------- helpers ----------------
__device__ __forceinline__ uint32_t smem_u32(const void* p) {
    uint32_t a;
    asm("{ .reg .u64 t; cvta.to.shared.u64 t, %1; cvt.u32.u64 %0, t; }" : "=r"(a) : "l"(p));
    return a;
}
__device__ __forceinline__ uint32_t swz128(uint32_t off) { return off ^ ((off >> 3) & 0x70); }
__device__ __forceinline__ uint32_t swz64(uint32_t off)  { return off ^ ((off >> 3) & 0x30); }
__device__ __forceinline__ void cp16(uint32_t s, const void* g) {
    asm volatile("cp.async.cg.shared.global [%0], [%1], 16;" :: "r"(s), "l"(g));
}
#define CP_COMMIT() asm volatile("cp.async.commit_group;" ::: "memory")
#define CP_WAIT(n)  asm volatile("cp.async.wait_group %0;" :: "n"(n) : "memory")

__device__ __forceinline__ void ldsm4(uint32_t r[4], uint32_t addr) {
    asm volatile("ldmatrix.sync.aligned.m8n8.x4.shared.b16 {%0,%1,%2,%3}, [%4];"
                 : "=r"(r[0]), "=r"(r[1]), "=r"(r[2]), "=r"(r[3]) : "r"(addr));
}
__device__ __forceinline__ void ldsm4t(uint32_t r[4], uint32_t addr) {
    asm volatile("ldmatrix.sync.aligned.m8n8.x4.trans.shared.b16 {%0,%1,%2,%3}, [%4];"
                 : "=r"(r[0]), "=r"(r[1]), "=r"(r[2]), "=r"(r[3]) : "r"(addr));
}
__device__ __forceinline__ void mma_f16(float d[4], const uint32_t a[4],
                                        uint32_t b0, uint32_t b1) {
    asm volatile(
        "mma.sync.aligned.m16n8k16.row.col.f32.f16.f16.f32 "
        "{%0,%1,%2,%3}, {%4,%5,%6,%7}, {%8,%9}, {%0,%1,%2,%3};"
        : "+f"(d[0]), "+f"(d[1]), "+f"(d[2]), "+f"(d[3])
        : "r"(a[0]), "r"(a[1]), "r"(a[2]), "r"(a[3]), "r"(b0), "r"(b1));
}
__device__ __forceinline__ uint32_t pack_f16x2(float v0, float v1) {
    __half2 h = __floats2half2_rn(v0, v1);
    return *reinterpret_cast<uint32_t*>(&h);
}
__device__ __forceinline__ void split2h(float v0, float v1, uint32_t& ph, uint32_t& pl) {
    __half h0 = __float2half_rn(v0), h1 = __float2half_rn(v1);
    __half2 hh = __halves2half2(h0, h1);
    ph = *reinterpret_cast<uint32_t*>(&hh);
    __half l0 = __float2half_rn(v0 - __half2float(h0));
    __half l1 = __float2half_rn(v1 - __half2float(h1));
    __half2 ll = __halves2half2(l0, l1);
    pl = *reinterpret_cast<uint32_t*>(&ll);
}

// ---------------- fused split ----------------
#define XN4 (M_TOT * D_MODEL / 4)
#define WN4 (WSZ / 4)

__global__ __launch_bounds__(256) void split_all(
    const float4* __restrict__ x,
    const float4* __restrict__ wq, const float4* __restrict__ wk,
    const float4* __restrict__ wv, const float4* __restrict__ wp,
    uint32_t* __restrict__ xhi,
    uint32_t* __restrict__ whi, uint32_t* __restrict__ wlo)
{
    int i = blockIdx.x * 256 + threadIdx.x;
    if (i < XN4) {
        float4 v = x[i];
        xhi[2 * i + 0] = pack_f16x2(v.x, v.y);
        xhi[2 * i + 1] = pack_f16x2(v.z, v.w);
        return;
    }
    int j = i - XN4;
    int w = j >> 18;
    int off = j & (WN4 - 1);
    const float4* src = (w == 0) ? wq : (w == 1) ? wk : (w == 2) ? wv : wp;
    uint32_t* hi = whi + (size_t)w * (WSZ / 2);
    uint32_t* lo = wlo + (size_t)w * (WSZ / 2);
    float4 v = src[off];
    uint32_t h0, l0, h1, l1;
    split2h(v.x * 256.0f, v.y * 256.0f, h0, l0);
    split2h(v.z * 256.0f, v.w * 256.0f, h1, l1);
    hi[2 * off + 0] = h0;
    hi[2 * off + 1] = h1;
    lo[2 * off + 0] = l0;
    lo[2 * off + 1] = l1;
}

// ---------------- HMMA fp16 2-product GEMM (BK=32, SW64, 3-stage) ----------------
// C = Ah * (256*Wh + 256*Wl) * 2^-8 + bias
// MODE 1 (QKV): q/k -> fp16 hi/lo of 16*C; v -> single fp16 of 16*C.
// MODE 2 (out-proj): fp32 C.
#define T_B    8192
#define NSTG   3
#define STG    (3 * T_B)
#define GEMM_SMEM (NSTG * STG)        // 73728
#define KCHUNKS (D_MODEL / 32)        // 32

__device__ __forceinline__ void load_stage3(
    uint32_t sbase, const __nv_bfloat16* a0,
    const __nv_bfloat16* b0, const __nv_bfloat16* b1, int kc, int tid)
{
    const __nv_bfloat16* gs[3] = {a0, b0, b1};
    #pragma unroll
    for (int t = 0; t < 3; t++) {
        uint32_t tb = sbase + t * T_B;
        const __nv_bfloat16* g = gs[t] + kc * 32;
        #pragma unroll
        for (int i = 0; i < 2; i++) {
            int u = i * 256 + tid;
            int r = u >> 2, c4 = u & 3;
            cp16(tb + swz64(r * 64 + c4 * 16), g + (size_t)r * D_MODEL + c4 * 8);
        }
    }
}

template <int MODE>
__global__ __launch_bounds__(256, 2) void gemm_hmma(
    const __nv_bfloat16* __restrict__ Ahi,
    const __nv_bfloat16* __restrict__ Whi, const __nv_bfloat16* __restrict__ Wlo,
    const float* __restrict__ biasQ, const float* __restrict__ biasK,
    const float* __restrict__ biasV,
    float* __restrict__ C,
    __nv_bfloat16* __restrict__ QH, __nv_bfloat16* __restrict__ QL,
    __nv_bfloat16* __restrict__ KH, __nv_bfloat16* __restrict__ KL,
    __nv_bfloat16* __restrict__ V16)
{
    extern __shared__ __align__(1024) char smem[];
    const uint32_t sb = smem_u32(smem);
    const int tid = threadIdx.x;
    const int wid = tid >> 5, lane = tid & 31;
    const int which = blockIdx.x >> 3;
    const int n0 = (blockIdx.x & 7) * 128;
    const int m0 = blockIdx.y * 128;
    const int wm = (wid >> 1) * 32;
    const int wn = (wid & 1) * 64;
    const int gid = lane >> 2, tig = lane & 3;

    const float* bias = (which == 0) ? biasQ : (which == 1) ? biasK : biasV;
    __nv_bfloat16* Chi = (which == 0) ? QH : (which == 1) ? KH : V16;
    __nv_bfloat16* Clo = (which == 0) ? QL : KL;    // unused for which==2

    const __nv_bfloat16* a0 = Ahi + (size_t)m0 * D_MODEL;
    const __nv_bfloat16* b0 = Whi + (size_t)which * WSZ + (size_t)n0 * D_MODEL;
    const __nv_bfloat16* b1 = Wlo + (size_t)which * WSZ + (size_t)n0 * D_MODEL;

    const int a_row  = wm + (lane & 15);
    const int a_byte = ((lane >> 4) & 1) * 16;
    const int b_row  = wn + ((lane >> 4) & 1) * 8 + (lane & 7);
    const int b_byte = ((lane >> 3) & 1) * 16;

    float d[2][8][4];
    #pragma unroll
    for (int i = 0; i < 2; i++)
        #pragma unroll
        for (int j = 0; j < 8; j++)
            #pragma unroll
            for (int c = 0; c < 4; c++) d[i][j][c] = 0.0f;

    load_stage3(sb + 0 * STG, a0, b0, b1, 0, tid);
    CP_COMMIT();
    load_stage3(sb + 1 * STG, a0, b0, b1, 1, tid);
    CP_COMMIT();

    for (int kc = 0; kc < KCHUNKS; kc++) {
        if (kc + 1 < KCHUNKS) { CP_WAIT(1); } else { CP_WAIT(0); }
        __syncthreads();
        if (kc + 2 < KCHUNKS) {
            load_stage3(sb + ((kc + 2) % NSTG) * STG, a0, b0, b1, kc + 2, tid);
            CP_COMMIT();
        }
        const uint32_t st = sb + (kc % NSTG) * STG;

        #pragma unroll
        for (int ks = 0; ks < 2; ks++) {
            uint32_t ah[2][4];
            #pragma unroll
            for (int am = 0; am < 2; am++) {
                uint32_t off = swz64((uint32_t)(a_row + am * 16) * 64 + a_byte + ks * 32);
                ldsm4(ah[am], st + off);
            }
            uint32_t bh[8][2], bl[8][2];
            #pragma unroll
            for (int pr = 0; pr < 4; pr++) {
                uint32_t off = swz64((uint32_t)(b_row + pr * 16) * 64 + b_byte + ks * 32);
                uint32_t r[4];
                ldsm4(r, st + 1 * T_B + off);
                bh[2 * pr][0] = r[0]; bh[2 * pr][1] = r[1];
                bh[2 * pr + 1][0] = r[2]; bh[2 * pr + 1][1] = r[3];
                ldsm4(r, st + 2 * T_B + off);
                bl[2 * pr][0] = r[0]; bl[2 * pr][1] = r[1];
                bl[2 * pr + 1][0] = r[2]; bl[2 * pr + 1][1] = r[3];
            }
            #pragma unroll
            for (int am = 0; am < 2; am++)
                #pragma unroll
                for (int bn = 0; bn < 8; bn++) {
                    mma_f16(d[am][bn], ah[am], bh[bn][0], bh[bn][1]);
                    mma_f16(d[am][bn], ah[am], bl[bn][0], bl[bn][1]);
                }
        }
    }

    const float osc = 1.0f / 256.0f;
    #pragma unroll
    for (int am = 0; am < 2; am++) {
        const int row = m0 + wm + am * 16 + gid;
        #pragma unroll
        for (int bn = 0; bn < 8; bn++) {
            const int col = n0 + wn + bn * 8 + tig * 2;
            const float bv0 = __ldg(&bias[col]);
            const float bv1 = __ldg(&bias[col + 1]);
            float v0 = d[am][bn][0] * osc + bv0, v1 = d[am][bn][1] * osc + bv1;
            float v2 = d[am][bn][2] * osc + bv0, v3 = d[am][bn][3] * osc + bv1;
            if (MODE == 1) {
                if (which == 2) {
                    // V: single fp16 of 16*val
                    *(uint32_t*)&Chi[(size_t)row * D_MODEL + col] =
                        pack_f16x2(v0 * 16.0f, v1 * 16.0f);
                    *(uint32_t*)&Chi[(size_t)(row + 8) * D_MODEL + col] =
                        pack_f16x2(v2 * 16.0f, v3 * 16.0f);
                } else {
                    uint32_t h, l;
                    split2h(v0 * 16.0f, v1 * 16.0f, h, l);
                    *(uint32_t*)&Chi[(size_t)row * D_MODEL + col] = h;
                    *(uint32_t*)&Clo[(size_t)row * D_MODEL + col] = l;
                    split2h(v2 * 16.0f, v3 * 16.0f, h, l);
                    *(uint32_t*)&Chi[(size_t)(row + 8) * D_MODEL + col] = h;
                    *(uint32_t*)&Clo[(size_t)(row + 8) * D_MODEL + col] = l;
                }
            } else {
                *(float2*)&C[(size_t)row * D_MODEL + col] = make_float2(v0, v1);
                *(float2*)&C[(size_t)(row + 8) * D_MODEL + col] = make_float2(v2, v3);
            }
        }
    }
}

// ---------------- HMMA flash attention (fp16, LPT, 2-stage, V single) ----------------
// Inputs hold 16*q, 16*k, 16*v. SC folds in 2^-8. PV = 1 product.
#define AQ 128
#define KV_STG 24576                    // khi, klo, v16 @ 8192 each
#define ATT_SMEM (2 * AQ * 128 + 2 * KV_STG)   // 81920

__global__ __launch_bounds__(256) void attn_hmma(
    const __nv_bfloat16* __restrict__ Qhi, const __nv_bfloat16* __restrict__ Qlo,
    const __nv_bfloat16* __restrict__ Khi, const __nv_bfloat16* __restrict__ Klo,
    const __nv_bfloat16* __restrict__ V16,
    __nv_bfloat16* __restrict__ Y)
{
    extern __shared__ __align__(1024) char smA[];
    const uint32_t sb = smem_u32(smA);
    const int tid = threadIdx.x, wid = tid >> 5, lane = tid & 31;
    const int gid = lane >> 2, tig = lane & 3;
    const int qblk = gridDim.y - 1 - blockIdx.y;   // LPT
    const int bh = blockIdx.x;
    const int b = bh >> 4, h = bh & 15;
    const size_t base = ((size_t)b * SEQ) * D_MODEL + (size_t)h * HEAD_DIM;

    const uint32_t sQh = sb;
    const uint32_t sQl = sb + AQ * 128;
    const uint32_t sKV = sb + 2 * AQ * 128;

    {
        const __nv_bfloat16* q0 = Qhi + base + (size_t)qblk * AQ * D_MODEL;
        const __nv_bfloat16* q1 = Qlo + base + (size_t)qblk * AQ * D_MODEL;
        #pragma unroll
        for (int i = 0; i < 4; i++) {
            int u = i * 256 + tid;
            int r = u >> 3, c = u & 7;
            cp16(sQh + swz128(r * 128 + c * 16), q0 + (size_t)r * D_MODEL + c * 8);
            cp16(sQl + swz128(r * 128 + c * 16), q1 + (size_t)r * D_MODEL + c * 8);
        }
    }
    CP_COMMIT();

    const int nkt = 2 * qblk + 2;

    {
        const __nv_bfloat16* srcs[3] = {Khi + base, Klo + base, V16 + base};
        #pragma unroll
        for (int t = 0; t < 3; t++)
            #pragma unroll
            for (int i = 0; i < 2; i++) {
                int u = i * 256 + tid;
                int r = u >> 3, c = u & 7;
                cp16(sKV + t * 8192 + swz128(r * 128 + c * 16),
                     srcs[t] + (size_t)r * D_MODEL + c * 8);
            }
    }
    CP_COMMIT();
    CP_WAIT(1);
    __syncthreads();

    uint32_t qh[4][4], ql[4][4];
    {
        const int ar = wid * 16 + (lane & 15);
        const int ab = ((lane >> 4) & 1) * 16;
        #pragma unroll
        for (int ks = 0; ks < 4; ks++) {
            ldsm4(qh[ks], sQh + swz128((uint32_t)ar * 128 + ab + ks * 32));
            ldsm4(ql[ks], sQl + swz128((uint32_t)ar * 128 + ab + ks * 32));
        }
    }

    float o[8][4];
    #pragma unroll
    for (int nt = 0; nt < 8; nt++)
        #pragma unroll
        for (int j = 0; j < 4; j++) o[nt][j] = 0.0f;
    float m0 = -1e30f, m1 = -1e30f, l0 = 0.0f, l1 = 0.0f;

    const int qr0 = qblk * AQ + wid * 16 + gid;
    const int row_min = qblk * AQ + wid * 16;
    const int row_max = row_min + 15;

    const int sbr = ((lane >> 4) & 1) * 8 + (lane & 7);
    const int sbb = ((lane >> 3) & 1) * 16;
    const int vrr = lane & 15;
    const int vbb = ((lane >> 4) & 1) * 16;

    const float SC = 0.125f * 1.44269504f / 256.0f;

    for (int kt = 0; kt < nkt; kt++) {
        const uint32_t st = sKV + (uint32_t)(kt & 1) * KV_STG;
        __syncthreads();
        if (kt + 1 < nkt) {
            const size_t koff = base + (size_t)(kt + 1) * 64 * D_MODEL;
            const __nv_bfloat16* srcs[3] = {Khi + koff, Klo + koff, V16 + koff};
            const uint32_t dst = sKV + (uint32_t)((kt + 1) & 1) * KV_STG;
            #pragma unroll
            for (int t = 0; t < 3; t++)
                #pragma unroll
                for (int i = 0; i < 2; i++) {
                    int u = i * 256 + tid;
                    int r = u >> 3, c = u & 7;
                    cp16(dst + t * 8192 + swz128(r * 128 + c * 16),
                         srcs[t] + (size_t)r * D_MODEL + c * 8);
                }
            CP_COMMIT();
            CP_WAIT(1);
        } else {
            CP_WAIT(0);
        }
        __syncthreads();

        if (kt * 64 > row_max) continue;

        float s[8][4];
        #pragma unroll
        for (int nt = 0; nt < 8; nt++)
            #pragma unroll
            for (int j = 0; j < 4; j++) s[nt][j] = 0.0f;

        #pragma unroll
        for (int ks = 0; ks < 4; ks++) {
            #pragma unroll
            for (int np = 0; np < 4; np++) {
                uint32_t off = swz128((uint32_t)(np * 16 + sbr) * 128 + sbb + ks * 32);
                uint32_t rh[4], rl[4];
                ldsm4(rh, st + off);
                ldsm4(rl, st + 8192 + off);
                mma_f16(s[2 * np],     qh[ks], rh[0], rh[1]);
                mma_f16(s[2 * np],     qh[ks], rl[0], rl[1]);
                mma_f16(s[2 * np],     ql[ks], rh[0], rh[1]);
                mma_f16(s[2 * np + 1], qh[ks], rh[2], rh[3]);
                mma_f16(s[2 * np + 1], qh[ks], rl[2], rl[3]);
                mma_f16(s[2 * np + 1], ql[ks], rh[2], rh[3]);
            }
        }

        const bool need_mask = (kt * 64 + 63 > row_min);
        #pragma unroll
        for (int nt = 0; nt < 8; nt++) {
            #pragma unroll
            for (int j = 0; j < 4; j++) s[nt][j] *= SC;
            if (need_mask) {
                const int kc = kt * 64 + nt * 8 + 2 * tig;
                if (kc     > qr0)     s[nt][0] = -1e30f;
                if (kc + 1 > qr0)     s[nt][1] = -1e30f;
                if (kc     > qr0 + 8) s[nt][2] = -1e30f;
                if (kc + 1 > qr0 + 8) s[nt][3] = -1e30f;
            }
        }

        float mx0 = -1e30f, mx1 = -1e30f;
        #pragma unroll
        for (int nt = 0; nt < 8; nt++) {
            mx0 = fmaxf(mx0, fmaxf(s[nt][0], s[nt][1]));
            mx1 = fmaxf(mx1, fmaxf(s[nt][2], s[nt][3]));
        }
        mx0 = fmaxf(mx0, __shfl_xor_sync(0xffffffffu, mx0, 1));
        mx0 = fmaxf(mx0, __shfl_xor_sync(0xffffffffu, mx0, 2));
        mx1 = fmaxf(mx1, __shfl_xor_sync(0xffffffffu, mx1, 1));
        mx1 = fmaxf(mx1, __shfl_xor_sync(0xffffffffu, mx1, 2));
        const float nm0 = fmaxf(m0, mx0), nm1 = fmaxf(m1, mx1);
        const float c0 = exp2f(m0 - nm0), c1 = exp2f(m1 - nm1);
        m0 = nm0; m1 = nm1;

        uint32_t pA[8], pB[8];
        float la0 = 0.0f, la1 = 0.0f;
        #pragma unroll
        for (int nt = 0; nt < 8; nt++) {
            float p0 = exp2f(s[nt][0] - m0), p1 = exp2f(s[nt][1] - m0);
            float p2 = exp2f(s[nt][2] - m1), p3 = exp2f(s[nt][3] - m1);
            la0 += p0 + p1; la1 += p2 + p3;
            pA[nt] = pack_f16x2(p0, p1);
            pB[nt] = pack_f16x2(p2, p3);
        }
        la0 += __shfl_xor_sync(0xffffffffu, la0, 1);
        la0 += __shfl_xor_sync(0xffffffffu, la0, 2);
        la1 += __shfl_xor_sync(0xffffffffu, la1, 1);
        la1 += __shfl_xor_sync(0xffffffffu, la1, 2);
        l0 = l0 * c0 + la0;
        l1 = l1 * c1 + la1;
        #pragma unroll
        for (int nt = 0; nt < 8; nt++) {
            o[nt][0] *= c0; o[nt][1] *= c0;
            o[nt][2] *= c1; o[nt][3] *= c1;
        }

        // ---- O += P V (single product) ----
        #pragma unroll
        for (int kk = 0; kk < 4; kk++) {
            uint32_t aH[4] = {pA[2 * kk], pB[2 * kk], pA[2 * kk + 1], pB[2 * kk + 1]};
            #pragma unroll
            for (int np = 0; np < 4; np++) {
                uint32_t off = swz128((uint32_t)(kk * 16 + vrr) * 128 + vbb + np * 32);
                uint32_t rv[4];
                ldsm4t(rv, st + 16384 + off);
                mma_f16(o[2 * np],     aH, rv[0], rv[1]);
                mma_f16(o[2 * np + 1], aH, rv[2], rv[3]);
            }
        }
    }

    // epilogue: y = o/(16*l), single fp16
    const float i0 = 1.0f / (16.0f * l0), i1 = 1.0f / (16.0f * l1);
    const size_t r0a = base + (size_t)qr0 * D_MODEL;
    const size_t r1a = base + (size_t)(qr0 + 8) * D_MODEL;
    #pragma unroll
    for (int nt = 0; nt < 8; nt++) {
        const int col = nt * 8 + 2 * tig;
        *(uint32_t*)&Y[r0a + col] = pack_f16x2(o[nt][0] * i0, o[nt][1] * i0);
        *(uint32_t*)&Y[r1a + col] = pack_f16x2(o[nt][2] * i1, o[nt][3] * i1);
    }
}

// ---------------- launch ----------------
extern "C" void kernel_launch(void* const* d_in, const int* in_sizes, int n_in,
                              void* d_out, int out_size)
{
    const float* x  = (const float*)d_in[0];
    const float* Wq = (const float*)d_in[1];
    const float* bq = (const float*)d_in[2];
    const float* Wk = (const float*)d_in[3];
    const float* bk = (const float*)d_in[4];
    const float* Wv = (const float*)d_in[5];
    const float* bv = (const float*)d_in[6];
    const float* Wp = (const float*)d_in[7];
    const float* bp = (const float*)d_in[8];
    float* out = (float*)d_out;

    __nv_bfloat16 *qhi, *qlo, *khi, *klo, *v16, *yhi, *xhi, *whi, *wlo;
    cudaGetSymbolAddress((void**)&qhi, g_qhi);
    cudaGetSymbolAddress((void**)&qlo, g_qlo);
    cudaGetSymbolAddress((void**)&khi, g_khi);
    cudaGetSymbolAddress((void**)&klo, g_klo);
    cudaGetSymbolAddress((void**)&v16, g_v16);
    cudaGetSymbolAddress((void**)&yhi, g_yhi);
    cudaGetSymbolAddress((void**)&xhi, g_xhi);
    cudaGetSymbolAddress((void**)&whi, g_whi);
    cudaGetSymbolAddress((void**)&wlo, g_wlo);

    cudaFuncSetAttribute(gemm_hmma<1>,
                         cudaFuncAttributeMaxDynamicSharedMemorySize, GEMM_SMEM);
    cudaFuncSetAttribute(gemm_hmma<2>,
                         cudaFuncAttributeMaxDynamicSharedMemorySize, GEMM_SMEM);
    cudaFuncSetAttribute(attn_hmma,
                         cudaFuncAttributeMaxDynamicSharedMemorySize, ATT_SMEM);

    split_all<<<(XN4 + 4 * WN4) / 256, 256>>>(
        (const float4*)x, (const float4*)Wq, (const float4*)Wk,
        (const float4*)Wv, (const float4*)Wp,
        (uint32_t*)xhi, (uint32_t*)whi, (uint32_t*)wlo);

    gemm_hmma<1><<<dim3(24, 32), 256, GEMM_SMEM>>>(
        xhi, whi, wlo, bq, bk, bv,
        nullptr, qhi, qlo, khi, klo, v16);

    attn_hmma<<<dim3(BATCH * N_HEADS, SEQ / AQ), 256, ATT_SMEM>>>(
        qhi, qlo, khi, klo, v16, yhi);

    gemm_hmma<2><<<dim3(8, 32), 256, GEMM_SMEM>>>(
        yhi, whi + 3u * WSZ, wlo + 3u * WSZ, bp, nullptr, nullptr,
        out, nullptr, nullptr, nullptr, nullptr, nullptr);
}

// round 15
// speedup vs baseline: 2.7985x; 1.6352x over previous
#include <cuda_runtime.h>
#include <cuda_bf16.h>
#include <cuda_fp16.h>
#include <cstdint>

#define D_MODEL  1024
#define N_HEADS  16
#define HEAD_DIM 64
#define BATCH    2
#define SEQ      2048
#define M_TOT    (BATCH * SEQ)   // 4096
#define WSZ      (D_MODEL * D_MODEL)

// ---------------- scratch (fp16 bits in bf16 containers) ----------------
// q/k/v: fp16 of 16*val. y: fp16 of 16*y. x: fp16 of 16*x. w: fp16 of 256*w.
__device__ __align__(1024) __nv_bfloat16 g_q16[M_TOT * D_MODEL];
__device__ __align__(1024) __nv_bfloat16 g_k16[M_TOT * D_MODEL];
__device__ __align__(1024) __nv_bfloat16 g_v16[M_TOT * D_MODEL];
__device__ __align__(1024) __nv_bfloat16 g_y16[M_TOT * D_MODEL];
__device__ __align__(1024) __nv_bfloat16 g_x16[M_TOT * D_MODEL];
__device__ __align__(1024) __nv_bfloat16 g_w256[4u * WSZ];

// ---------------- helpers ----------------
__device__ __forceinline__ uint32_t smem_u32(const void* p) {
    uint32_t a;
    asm("{ .reg .u64 t; cvta.to.shared.u64 t, %1; cvt.u32.u64 %0, t; }" : "=r"(a) : "l"(p));
    return a;
}
__device__ __forceinline__ uint32_t swz128(uint32_t off) { return off ^ ((off >> 3) & 0x70); }
__device__ __forceinline__ uint32_t swz64(uint32_t off)  { return off ^ ((off >> 3) & 0x30); }
__device__ __forceinline__ void cp16(uint32_t s, const void* g) {
    asm volatile("cp.async.cg.shared.global [%0], [%1], 16;" :: "r"(s), "l"(g));
}
#define CP_COMMIT() asm volatile("cp.async.commit_group;" ::: "memory")
#define CP_WAIT(n)  asm volatile("cp.async.wait_group %0;" :: "n"(n) : "memory")

__device__ __forceinline__ void ldsm4(uint32_t r[4], uint32_t addr) {
    asm volatile("ldmatrix.sync.aligned.m8n8.x4.shared.b16 {%0,%1,%2,%3}, [%4];"
                 : "=r"(r[0]), "=r"(r[1]), "=r"(r[2]), "=r"(r[3]) : "r"(addr));
}
__device__ __forceinline__ void ldsm4t(uint32_t r[4], uint32_t addr) {
    asm volatile("ldmatrix.sync.aligned.m8n8.x4.trans.shared.b16 {%0,%1,%2,%3}, [%4];"
                 : "=r"(r[0]), "=r"(r[1]), "=r"(r[2]), "=r"(r[3]) : "r"(addr));
}
__device__ __forceinline__ void mma_f16(float d[4], const uint32_t a[4],
                                        uint32_t b0, uint32_t b1) {
    asm volatile(
        "mma.sync.aligned.m16n8k16.row.col.f32.f16.f16.f32 "
        "{%0,%1,%2,%3}, {%4,%5,%6,%7}, {%8,%9}, {%0,%1,%2,%3};"
        : "+f"(d[0]), "+f"(d[1]), "+f"(d[2]), "+f"(d[3])
        : "r"(a[0]), "r"(a[1]), "r"(a[2]), "r"(a[3]), "r"(b0), "r"(b1));
}
__device__ __forceinline__ uint32_t pack_f16x2(float v0, float v1) {
    __half2 h = __floats2half2_rn(v0, v1);
    return *reinterpret_cast<uint32_t*>(&h);
}

// ---------------- fused split: x*16 + weights*256, single fp16 ----------------
#define XN4 (M_TOT * D_MODEL / 4)
#define WN4 (WSZ / 4)

__global__ __launch_bounds__(256) void split_all(
    const float4* __restrict__ x,
    const float4* __restrict__ wq, const float4* __restrict__ wk,
    const float4* __restrict__ wv, const float4* __restrict__ wp,
    uint32_t* __restrict__ x16, uint32_t* __restrict__ w256)
{
    int i = blockIdx.x * 256 + threadIdx.x;
    if (i < XN4) {
        float4 v = x[i];
        x16[2 * i + 0] = pack_f16x2(v.x * 16.0f, v.y * 16.0f);
        x16[2 * i + 1] = pack_f16x2(v.z * 16.0f, v.w * 16.0f);
        return;
    }
    int j = i - XN4;
    int w = j >> 18;
    int off = j & (WN4 - 1);
    const float4* src = (w == 0) ? wq : (w == 1) ? wk : (w == 2) ? wv : wp;
    uint32_t* dst = w256 + (size_t)w * (WSZ / 2);
    float4 v = src[off];
    dst[2 * off + 0] = pack_f16x2(v.x * 256.0f, v.y * 256.0f);
    dst[2 * off + 1] = pack_f16x2(v.z * 256.0f, v.w * 256.0f);
}

// ---------------- HMMA fp16 1-product GEMM (BK=32, SW64, 3-stage) ----------------
// C = (16A)*(256W) * 2^-12 + bias
// MODE 1 (QKV): outputs fp16 of 16*C. MODE 2 (out-proj): fp32 C.
#define T_B    8192
#define NSTG   3
#define STG    (2 * T_B)              // {A, W}
#define GEMM_SMEM (NSTG * STG)        // 49152 -> 2 CTAs/SM
#define KCHUNKS (D_MODEL / 32)        // 32

__device__ __forceinline__ void load_stage2(
    uint32_t sbase, const __nv_bfloat16* a0, const __nv_bfloat16* b0,
    int kc, int tid)
{
    const __nv_bfloat16* gs[2] = {a0, b0};
    #pragma unroll
    for (int t = 0; t < 2; t++) {
        uint32_t tb = sbase + t * T_B;
        const __nv_bfloat16* g = gs[t] + kc * 32;
        #pragma unroll
        for (int i = 0; i < 2; i++) {
            int u = i * 256 + tid;
            int r = u >> 2, c4 = u & 3;
            cp16(tb + swz64(r * 64 + c4 * 16), g + (size_t)r * D_MODEL + c4 * 8);
        }
    }
}

template <int MODE>
__global__ __launch_bounds__(256, 2) void gemm_hmma(
    const __nv_bfloat16* __restrict__ A16,
    const __nv_bfloat16* __restrict__ W256,
    const float* __restrict__ biasQ, const float* __restrict__ biasK,
    const float* __restrict__ biasV,
    float* __restrict__ C,
    __nv_bfloat16* __restrict__ Q16, __nv_bfloat16* __restrict__ K16,
    __nv_bfloat16* __restrict__ V16)
{
    extern __shared__ __align__(1024) char smem[];
    const uint32_t sb = smem_u32(smem);
    const int tid = threadIdx.x;
    const int wid = tid >> 5, lane = tid & 31;
    const int which = blockIdx.x >> 3;
    const int n0 = (blockIdx.x & 7) * 128;
    const int m0 = blockIdx.y * 128;
    const int wm = (wid >> 1) * 32;
    const int wn = (wid & 1) * 64;
    const int gid = lane >> 2, tig = lane & 3;

    const float* bias = (which == 0) ? biasQ : (which == 1) ? biasK : biasV;
    __nv_bfloat16* Cout = (which == 0) ? Q16 : (which == 1) ? K16 : V16;

    const __nv_bfloat16* a0 = A16 + (size_t)m0 * D_MODEL;
    const __nv_bfloat16* b0 = W256 + (size_t)which * WSZ + (size_t)n0 * D_MODEL;

    const int a_row  = wm + (lane & 15);
    const int a_byte = ((lane >> 4) & 1) * 16;
    const int b_row  = wn + ((lane >> 4) & 1) * 8 + (lane & 7);
    const int b_byte = ((lane >> 3) & 1) * 16;

    float d[2][8][4];
    #pragma unroll
    for (int i = 0; i < 2; i++)
        #pragma unroll
        for (int j = 0; j < 8; j++)
            #pragma unroll
            for (int c = 0; c < 4; c++) d[i][j][c] = 0.0f;

    load_stage2(sb + 0 * STG, a0, b0, 0, tid);
    CP_COMMIT();
    load_stage2(sb + 1 * STG, a0, b0, 1, tid);
    CP_COMMIT();

    for (int kc = 0; kc < KCHUNKS; kc++) {
        if (kc + 1 < KCHUNKS) { CP_WAIT(1); } else { CP_WAIT(0); }
        __syncthreads();
        if (kc + 2 < KCHUNKS) {
            load_stage2(sb + ((kc + 2) % NSTG) * STG, a0, b0, kc + 2, tid);
            CP_COMMIT();
        }
        const uint32_t st = sb + (kc % NSTG) * STG;

        #pragma unroll
        for (int ks = 0; ks < 2; ks++) {
            uint32_t ah[2][4];
            #pragma unroll
            for (int am = 0; am < 2; am++) {
                uint32_t off = swz64((uint32_t)(a_row + am * 16) * 64 + a_byte + ks * 32);
                ldsm4(ah[am], st + off);
            }
            uint32_t bh[8][2];
            #pragma unroll
            for (int pr = 0; pr < 4; pr++) {
                uint32_t off = swz64((uint32_t)(b_row + pr * 16) * 64 + b_byte + ks * 32);
                uint32_t r[4];
                ldsm4(r, st + T_B + off);
                bh[2 * pr][0] = r[0]; bh[2 * pr][1] = r[1];
                bh[2 * pr + 1][0] = r[2]; bh[2 * pr + 1][1] = r[3];
            }
            #pragma unroll
            for (int am = 0; am < 2; am++)
                #pragma unroll
                for (int bn = 0; bn < 8; bn++)
                    mma_f16(d[am][bn], ah[am], bh[bn][0], bh[bn][1]);
        }
    }

    const float osc = 1.0f / 4096.0f;    // undo 16*256
    #pragma unroll
    for (int am = 0; am < 2; am++) {
        const int row = m0 + wm + am * 16 + gid;
        #pragma unroll
        for (int bn = 0; bn < 8; bn++) {
            const int col = n0 + wn + bn * 8 + tig * 2;
            const float bv0 = __ldg(&bias[col]);
            const float bv1 = __ldg(&bias[col + 1]);
            float v0 = d[am][bn][0] * osc + bv0, v1 = d[am][bn][1] * osc + bv1;
            float v2 = d[am][bn][2] * osc + bv0, v3 = d[am][bn][3] * osc + bv1;
            if (MODE == 1) {
                *(uint32_t*)&Cout[(size_t)row * D_MODEL + col] =
                    pack_f16x2(v0 * 16.0f, v1 * 16.0f);
                *(uint32_t*)&Cout[(size_t)(row + 8) * D_MODEL + col] =
                    pack_f16x2(v2 * 16.0f, v3 * 16.0f);
            } else {
                *(float2*)&C[(size_t)row * D_MODEL + col] = make_float2(v0, v1);
                *(float2*)&C[(size_t)(row + 8) * D_MODEL + col] = make_float2(v2, v3);
            }
        }
    }
}

// ---------------- HMMA flash attention (fp16, all single, LPT, 2-stage) ----------------
// Inputs hold 16*q, 16*k, 16*v. S = 1 product, PV = 1 product.
#define AQ 128
#define KV_STG 16384                    // k16, v16 @ 8192 each
#define ATT_SMEM (AQ * 128 + 2 * KV_STG)   // 49152

__global__ __launch_bounds__(256) void attn_hmma(
    const __nv_bfloat16* __restrict__ Q16,
    const __nv_bfloat16* __restrict__ K16,
    const __nv_bfloat16* __restrict__ V16,
    __nv_bfloat16* __restrict__ Y16)
{
    extern __shared__ __align__(1024) char smA[];
    const uint32_t sb = smem_u32(smA);
    const int tid = threadIdx.x, wid = tid >> 5, lane = tid & 31;
    const int gid = lane >> 2, tig = lane & 3;
    const int qblk = gridDim.y - 1 - blockIdx.y;   // LPT
    const int bh = blockIdx.x;
    const int b = bh >> 4, h = bh & 15;
    const size_t base = ((size_t)b * SEQ) * D_MODEL + (size_t)h * HEAD_DIM;

    const uint32_t sQ = sb;
    const uint32_t sKV = sb + AQ * 128;

    {
        const __nv_bfloat16* q0 = Q16 + base + (size_t)qblk * AQ * D_MODEL;
        #pragma unroll
        for (int i = 0; i < 4; i++) {
            int u = i * 256 + tid;
            int r = u >> 3, c = u & 7;
            cp16(sQ + swz128(r * 128 + c * 16), q0 + (size_t)r * D_MODEL + c * 8);
        }
    }
    CP_COMMIT();

    const int nkt = 2 * qblk + 2;

    {
        const __nv_bfloat16* srcs[2] = {K16 + base, V16 + base};
        #pragma unroll
        for (int t = 0; t < 2; t++)
            #pragma unroll
            for (int i = 0; i < 2; i++) {
                int u = i * 256 + tid;
                int r = u >> 3, c = u & 7;
                cp16(sKV + t * 8192 + swz128(r * 128 + c * 16),
                     srcs[t] + (size_t)r * D_MODEL + c * 8);
            }
    }
    CP_COMMIT();
    CP_WAIT(1);
    __syncthreads();

    uint32_t qf[4][4];
    {
        const int ar = wid * 16 + (lane & 15);
        const int ab = ((lane >> 4) & 1) * 16;
        #pragma unroll
        for (int ks = 0; ks < 4; ks++)
            ldsm4(qf[ks], sQ + swz128((uint32_t)ar * 128 + ab + ks * 32));
    }

    float o[8][4];
    #pragma unroll
    for (int nt = 0; nt < 8; nt++)
        #pragma unroll
        for (int j = 0; j < 4; j++) o[nt][j] = 0.0f;
    float m0 = -1e30f, m1 = -1e30f, l0 = 0.0f, l1 = 0.0f;

    const int qr0 = qblk * AQ + wid * 16 + gid;
    const int row_min = qblk * AQ + wid * 16;
    const int row_max = row_min + 15;

    const int sbr = ((lane >> 4) & 1) * 8 + (lane & 7);
    const int sbb = ((lane >> 3) & 1) * 16;
    const int vrr = lane & 15;
    const int vbb = ((lane >> 4) & 1) * 16;

    const float SC = 0.125f * 1.44269504f / 256.0f;   // 16q*16k

    for (int kt = 0; kt < nkt; kt++) {
        const uint32_t st = sKV + (uint32_t)(kt & 1) * KV_STG;
        __syncthreads();
        if (kt + 1 < nkt) {
            const size_t koff = base + (size_t)(kt + 1) * 64 * D_MODEL;
            const __nv_bfloat16* srcs[2] = {K16 + koff, V16 + koff};
            const uint32_t dst = sKV + (uint32_t)((kt + 1) & 1) * KV_STG;
            #pragma unroll
            for (int t = 0; t < 2; t++)
                #pragma unroll
                for (int i = 0; i < 2; i++) {
                    int u = i * 256 + tid;
                    int r = u >> 3, c = u & 7;
                    cp16(dst + t * 8192 + swz128(r * 128 + c * 16),
                         srcs[t] + (size_t)r * D_MODEL + c * 8);
                }
            CP_COMMIT();
            CP_WAIT(1);
        } else {
            CP_WAIT(0);
        }
        __syncthreads();

        if (kt * 64 > row_max) continue;

        // ---- S = Q K^T (1 product) ----
        float s[8][4];
        #pragma unroll
        for (int nt = 0; nt < 8; nt++)
            #pragma unroll
            for (int j = 0; j < 4; j++) s[nt][j] = 0.0f;

        #pragma unroll
        for (int ks = 0; ks < 4; ks++) {
            #pragma unroll
            for (int np = 0; np < 4; np++) {
                uint32_t off = swz128((uint32_t)(np * 16 + sbr) * 128 + sbb + ks * 32);
                uint32_t rk[4];
                ldsm4(rk, st + off);
                mma_f16(s[2 * np],     qf[ks], rk[0], rk[1]);
                mma_f16(s[2 * np + 1], qf[ks], rk[2], rk[3]);
            }
        }

        const bool need_mask = (kt * 64 + 63 > row_min);
        #pragma unroll
        for (int nt = 0; nt < 8; nt++) {
            #pragma unroll
            for (int j = 0; j < 4; j++) s[nt][j] *= SC;
            if (need_mask) {
                const int kc = kt * 64 + nt * 8 + 2 * tig;
                if (kc     > qr0)     s[nt][0] = -1e30f;
                if (kc + 1 > qr0)     s[nt][1] = -1e30f;
                if (kc     > qr0 + 8) s[nt][2] = -1e30f;
                if (kc + 1 > qr0 + 8) s[nt][3] = -1e30f;
            }
        }

        float mx0 = -1e30f, mx1 = -1e30f;
        #pragma unroll
        for (int nt = 0; nt < 8; nt++) {
            mx0 = fmaxf(mx0, fmaxf(s[nt][0], s[nt][1]));
            mx1 = fmaxf(mx1, fmaxf(s[nt][2], s[nt][3]));
        }
        mx0 = fmaxf(mx0, __shfl_xor_sync(0xffffffffu, mx0, 1));
        mx0 = fmaxf(mx0, __shfl_xor_sync(0xffffffffu, mx0, 2));
        mx1 = fmaxf(mx1, __shfl_xor_sync(0xffffffffu, mx1, 1));
        mx1 = fmaxf(mx1, __shfl_xor_sync(0xffffffffu, mx1, 2));
        const float nm0 = fmaxf(m0, mx0), nm1 = fmaxf(m1, mx1);
        const float c0 = exp2f(m0 - nm0), c1 = exp2f(m1 - nm1);
        m0 = nm0; m1 = nm1;

        uint32_t pA[8], pB[8];
        float la0 = 0.0f, la1 = 0.0f;
        #pragma unroll
        for (int nt = 0; nt < 8; nt++) {
            float p0 = exp2f(s[nt][0] - m0), p1 = exp2f(s[nt][1] - m0);
            float p2 = exp2f(s[nt][2] - m1), p3 = exp2f(s[nt][3] - m1);
            la0 += p0 + p1; la1 += p2 + p3;
            pA[nt] = pack_f16x2(p0, p1);
            pB[nt] = pack_f16x2(p2, p3);
        }
        la0 += __shfl_xor_sync(0xffffffffu, la0, 1);
        la0 += __shfl_xor_sync(0xffffffffu, la0, 2);
        la1 += __shfl_xor_sync(0xffffffffu, la1, 1);
        la1 += __shfl_xor_sync(0xffffffffu, la1, 2);
        l0 = l0 * c0 + la0;
        l1 = l1 * c1 + la1;
        #pragma unroll
        for (int nt = 0; nt < 8; nt++) {
            o[nt][0] *= c0; o[nt][1] *= c0;
            o[nt][2] *= c1; o[nt][3] *= c1;
        }

        // ---- O += P V (1 product) ----
        #pragma unroll
        for (int kk = 0; kk < 4; kk++) {
            uint32_t aH[4] = {pA[2 * kk], pB[2 * kk], pA[2 * kk + 1], pB[2 * kk + 1]};
            #pragma unroll
            for (int np = 0; np < 4; np++) {
                uint32_t off = swz128((uint32_t)(kk * 16 + vrr) * 128 + vbb + np * 32);
                uint32_t rv[4];
                ldsm4t(rv, st + 8192 + off);
                mma_f16(o[2 * np],     aH, rv[0], rv[1]);
                mma_f16(o[2 * np + 1], aH, rv[2], rv[3]);
            }
        }
    }

    // epilogue: store 16*y = o/l as fp16
    const float i0 = 1.0f / l0, i1 = 1.0f / l1;
    const size_t r0a = base + (size_t)qr0 * D_MODEL;
    const size_t r1a = base + (size_t)(qr0 + 8) * D_MODEL;
    #pragma unroll
    for (int nt = 0; nt < 8; nt++) {
        const int col = nt * 8 + 2 * tig;
        *(uint32_t*)&Y16[r0a + col] = pack_f16x2(o[nt][0] * i0, o[nt][1] * i0);
        *(uint32_t*)&Y16[r1a + col] = pack_f16x2(o[nt][2] * i1, o[nt][3] * i1);
    }
}

// ---------------- launch ----------------
extern "C" void kernel_launch(void* const* d_in, const int* in_sizes, int n_in,
                              void* d_out, int out_size)
{
    const float* x  = (const float*)d_in[0];
    const float* Wq = (const float*)d_in[1];
    const float* bq = (const float*)d_in[2];
    const float* Wk = (const float*)d_in[3];
    const float* bk = (const float*)d_in[4];
    const float* Wv = (const float*)d_in[5];
    const float* bv = (const float*)d_in[6];
    const float* Wp = (const float*)d_in[7];
    const float* bp = (const float*)d_in[8];
    float* out = (float*)d_out;

    __nv_bfloat16 *q16, *k16, *v16, *y16, *x16, *w256;
    cudaGetSymbolAddress((void**)&q16, g_q16);
    cudaGetSymbolAddress((void**)&k16, g_k16);
    cudaGetSymbolAddress((void**)&v16, g_v16);
    cudaGetSymbolAddress((void**)&y16, g_y16);
    cudaGetSymbolAddress((void**)&x16, g_x16);
    cudaGetSymbolAddress((void**)&w256, g_w256);

    cudaFuncSetAttribute(gemm_hmma<1>,
                         cudaFuncAttributeMaxDynamicSharedMemorySize, GEMM_SMEM);
    cudaFuncSetAttribute(gemm_hmma<2>,
                         cudaFuncAttributeMaxDynamicSharedMemorySize, GEMM_SMEM);
    cudaFuncSetAttribute(attn_hmma,
                         cudaFuncAttributeMaxDynamicSharedMemorySize, ATT_SMEM);

    split_all<<<(XN4 + 4 * WN4) / 256, 256>>>(
        (const float4*)x, (const float4*)Wq, (const float4*)Wk,
        (const float4*)Wv, (const float4*)Wp,
        (uint32_t*)x16, (uint32_t*)w256);

    gemm_hmma<1><<<dim3(24, 32), 256, GEMM_SMEM>>>(
        x16, w256, bq, bk, bv,
        nullptr, q16, k16, v16);

    attn_hmma<<<dim3(BATCH * N_HEADS, SEQ / AQ), 256, ATT_SMEM>>>(
        q16, k16, v16, y16);

    gemm_hmma<2><<<dim3(8, 32), 256, GEMM_SMEM>>>(
        y16, w256 + 3u * WSZ, bp, nullptr, nullptr,
        out, nullptr, nullptr, nullptr);
}

// round 16
// speedup vs baseline: 3.0770x; 1.0995x over previous
#include <cuda_runtime.h>
#include <cuda_bf16.h>
#include <cuda_fp16.h>
#include <cstdint>

#define D_MODEL  1024
#define N_HEADS  16
#define HEAD_DIM 64
#define BATCH    2
#define SEQ      2048
#define M_TOT    (BATCH * SEQ)   // 4096
#define WSZ      (D_MODEL * D_MODEL)

// ---------------- scratch (fp16 bits in bf16 containers) ----------------
__device__ __align__(1024) __nv_bfloat16 g_q16[M_TOT * D_MODEL];
__device__ __align__(1024) __nv_bfloat16 g_k16[M_TOT * D_MODEL];
__device__ __align__(1024) __nv_bfloat16 g_v16[M_TOT * D_MODEL];
__device__ __align__(1024) __nv_bfloat16 g_y16[M_TOT * D_MODEL];
__device__ __align__(1024) __nv_bfloat16 g_x16[M_TOT * D_MODEL];
__device__ __align__(1024) __nv_bfloat16 g_w256[4u * WSZ];

// ---------------- helpers ----------------
__device__ __forceinline__ uint32_t smem_u32(const void* p) {
    uint32_t a;
    asm("{ .reg .u64 t; cvta.to.shared.u64 t, %1; cvt.u32.u64 %0, t; }" : "=r"(a) : "l"(p));
    return a;
}
__device__ __forceinline__ uint32_t swz128(uint32_t off) { return off ^ ((off >> 3) & 0x70); }
__device__ __forceinline__ void cp16(uint32_t s, const void* g) {
    asm volatile("cp.async.cg.shared.global [%0], [%1], 16;" :: "r"(s), "l"(g));
}
#define CP_COMMIT() asm volatile("cp.async.commit_group;" ::: "memory")
#define CP_WAIT(n)  asm volatile("cp.async.wait_group %0;" :: "n"(n) : "memory")

__device__ __forceinline__ void ldsm4(uint32_t r[4], uint32_t addr) {
    asm volatile("ldmatrix.sync.aligned.m8n8.x4.shared.b16 {%0,%1,%2,%3}, [%4];"
                 : "=r"(r[0]), "=r"(r[1]), "=r"(r[2]), "=r"(r[3]) : "r"(addr));
}
__device__ __forceinline__ void ldsm4t(uint32_t r[4], uint32_t addr) {
    asm volatile("ldmatrix.sync.aligned.m8n8.x4.trans.shared.b16 {%0,%1,%2,%3}, [%4];"
                 : "=r"(r[0]), "=r"(r[1]), "=r"(r[2]), "=r"(r[3]) : "r"(addr));
}
__device__ __forceinline__ void mma_f16(float d[4], const uint32_t a[4],
                                        uint32_t b0, uint32_t b1) {
    asm volatile(
        "mma.sync.aligned.m16n8k16.row.col.f32.f16.f16.f32 "
        "{%0,%1,%2,%3}, {%4,%5,%6,%7}, {%8,%9}, {%0,%1,%2,%3};"
        : "+f"(d[0]), "+f"(d[1]), "+f"(d[2]), "+f"(d[3])
        : "r"(a[0]), "r"(a[1]), "r"(a[2]), "r"(a[3]), "r"(b0), "r"(b1));
}
__device__ __forceinline__ uint32_t pack_f16x2(float v0, float v1) {
    __half2 h = __floats2half2_rn(v0, v1);
    return *reinterpret_cast<uint32_t*>(&h);
}

// ---------------- fused split: x*16 + weights*256, single fp16 ----------------
#define XN4 (M_TOT * D_MODEL / 4)
#define WN4 (WSZ / 4)

__global__ __launch_bounds__(256) void split_all(
    const float4* __restrict__ x,
    const float4* __restrict__ wq, const float4* __restrict__ wk,
    const float4* __restrict__ wv, const float4* __restrict__ wp,
    uint32_t* __restrict__ x16, uint32_t* __restrict__ w256)
{
    int i = blockIdx.x * 256 + threadIdx.x;
    if (i < XN4) {
        float4 v = x[i];
        x16[2 * i + 0] = pack_f16x2(v.x * 16.0f, v.y * 16.0f);
        x16[2 * i + 1] = pack_f16x2(v.z * 16.0f, v.w * 16.0f);
        return;
    }
    int j = i - XN4;
    int w = j >> 18;
    int off = j & (WN4 - 1);
    const float4* src = (w == 0) ? wq : (w == 1) ? wk : (w == 2) ? wv : wp;
    uint32_t* dst = w256 + (size_t)w * (WSZ / 2);
    float4 v = src[off];
    dst[2 * off + 0] = pack_f16x2(v.x * 256.0f, v.y * 256.0f);
    dst[2 * off + 1] = pack_f16x2(v.z * 256.0f, v.w * 256.0f);
}

// ---------------- HMMA fp16 1-product GEMM (BK=64, SW128, 3-stage) ----------------
// C = (16A)*(256W) * 2^-12 + bias
// MODE 1 (QKV): outputs fp16 of 16*C. MODE 2 (out-proj): fp32 C.
#define T_B    16384                  // 128 rows x 64 fp16 (128B), SW128
#define NSTG   3
#define STG    (2 * T_B)              // {A, W} = 32768
#define GEMM_SMEM (NSTG * STG)        // 98304 -> 2 CTAs/SM (192KB <= 228KB)
#define KCHUNKS (D_MODEL / 64)        // 16

__device__ __forceinline__ void load_stage2(
    uint32_t sbase, const __nv_bfloat16* a0, const __nv_bfloat16* b0,
    int kc, int tid)
{
    const __nv_bfloat16* gs[2] = {a0, b0};
    #pragma unroll
    for (int t = 0; t < 2; t++) {
        uint32_t tb = sbase + t * T_B;
        const __nv_bfloat16* g = gs[t] + kc * 64;
        #pragma unroll
        for (int i = 0; i < 4; i++) {
            int u = i * 256 + tid;            // 0..1023 16B-chunks
            int r = u >> 3, c8 = u & 7;
            cp16(tb + swz128(r * 128 + c8 * 16), g + (size_t)r * D_MODEL + c8 * 8);
        }
    }
}

template <int MODE>
__global__ __launch_bounds__(256, 2) void gemm_hmma(
    const __nv_bfloat16* __restrict__ A16,
    const __nv_bfloat16* __restrict__ W256,
    const float* __restrict__ biasQ, const float* __restrict__ biasK,
    const float* __restrict__ biasV,
    float* __restrict__ C,
    __nv_bfloat16* __restrict__ Q16, __nv_bfloat16* __restrict__ K16,
    __nv_bfloat16* __restrict__ V16)
{
    extern __shared__ __align__(1024) char smem[];
    const uint32_t sb = smem_u32(smem);
    const int tid = threadIdx.x;
    const int wid = tid >> 5, lane = tid & 31;
    const int which = blockIdx.x >> 3;
    const int n0 = (blockIdx.x & 7) * 128;
    const int m0 = blockIdx.y * 128;
    const int wm = (wid >> 1) * 32;
    const int wn = (wid & 1) * 64;
    const int gid = lane >> 2, tig = lane & 3;

    const float* bias = (which == 0) ? biasQ : (which == 1) ? biasK : biasV;
    __nv_bfloat16* Cout = (which == 0) ? Q16 : (which == 1) ? K16 : V16;

    const __nv_bfloat16* a0 = A16 + (size_t)m0 * D_MODEL;
    const __nv_bfloat16* b0 = W256 + (size_t)which * WSZ + (size_t)n0 * D_MODEL;

    const int a_row  = wm + (lane & 15);
    const int a_byte = ((lane >> 4) & 1) * 16;
    const int b_row  = wn + ((lane >> 4) & 1) * 8 + (lane & 7);
    const int b_byte = ((lane >> 3) & 1) * 16;

    float d[2][8][4];
    #pragma unroll
    for (int i = 0; i < 2; i++)
        #pragma unroll
        for (int j = 0; j < 8; j++)
            #pragma unroll
            for (int c = 0; c < 4; c++) d[i][j][c] = 0.0f;

    load_stage2(sb + 0 * STG, a0, b0, 0, tid);
    CP_COMMIT();
    load_stage2(sb + 1 * STG, a0, b0, 1, tid);
    CP_COMMIT();

    for (int kc = 0; kc < KCHUNKS; kc++) {
        if (kc + 1 < KCHUNKS) { CP_WAIT(1); } else { CP_WAIT(0); }
        __syncthreads();
        if (kc + 2 < KCHUNKS) {
            load_stage2(sb + ((kc + 2) % NSTG) * STG, a0, b0, kc + 2, tid);
            CP_COMMIT();
        }
        const uint32_t st = sb + (kc % NSTG) * STG;

        #pragma unroll
        for (int ks = 0; ks < 4; ks++) {
            uint32_t ah[2][4];
            #pragma unroll
            for (int am = 0; am < 2; am++) {
                uint32_t off = swz128((uint32_t)(a_row + am * 16) * 128 + a_byte + ks * 32);
                ldsm4(ah[am], st + off);
            }
            uint32_t bh[8][2];
            #pragma unroll
            for (int pr = 0; pr < 4; pr++) {
                uint32_t off = swz128((uint32_t)(b_row + pr * 16) * 128 + b_byte + ks * 32);
                uint32_t r[4];
                ldsm4(r, st + T_B + off);
                bh[2 * pr][0] = r[0]; bh[2 * pr][1] = r[1];
                bh[2 * pr + 1][0] = r[2]; bh[2 * pr + 1][1] = r[3];
            }
            #pragma unroll
            for (int am = 0; am < 2; am++)
                #pragma unroll
                for (int bn = 0; bn < 8; bn++)
                    mma_f16(d[am][bn], ah[am], bh[bn][0], bh[bn][1]);
        }
    }

    const float osc = 1.0f / 4096.0f;    // undo 16*256
    #pragma unroll
    for (int am = 0; am < 2; am++) {
        const int row = m0 + wm + am * 16 + gid;
        #pragma unroll
        for (int bn = 0; bn < 8; bn++) {
            const int col = n0 + wn + bn * 8 + tig * 2;
            const float bv0 = __ldg(&bias[col]);
            const float bv1 = __ldg(&bias[col + 1]);
            float v0 = d[am][bn][0] * osc + bv0, v1 = d[am][bn][1] * osc + bv1;
            float v2 = d[am][bn][2] * osc + bv0, v3 = d[am][bn][3] * osc + bv1;
            if (MODE == 1) {
                *(uint32_t*)&Cout[(size_t)row * D_MODEL + col] =
                    pack_f16x2(v0 * 16.0f, v1 * 16.0f);
                *(uint32_t*)&Cout[(size_t)(row + 8) * D_MODEL + col] =
                    pack_f16x2(v2 * 16.0f, v3 * 16.0f);
            } else {
                *(float2*)&C[(size_t)row * D_MODEL + col] = make_float2(v0, v1);
                *(float2*)&C[(size_t)(row + 8) * D_MODEL + col] = make_float2(v2, v3);
            }
        }
    }
}

// ---------------- HMMA flash attention (fp16 single, LPT, 2-stage, 2 CTAs/SM) ----------------
#define AQ 128
#define KV_STG 16384                    // k16, v16 @ 8192 each
#define ATT_SMEM (AQ * 128 + 2 * KV_STG)   // 49152 -> 2 CTAs/SM

__global__ __launch_bounds__(256, 2) void attn_hmma(
    const __nv_bfloat16* __restrict__ Q16,
    const __nv_bfloat16* __restrict__ K16,
    const __nv_bfloat16* __restrict__ V16,
    __nv_bfloat16* __restrict__ Y16)
{
    extern __shared__ __align__(1024) char smA[];
    const uint32_t sb = smem_u32(smA);
    const int tid = threadIdx.x, wid = tid >> 5, lane = tid & 31;
    const int gid = lane >> 2, tig = lane & 3;
    const int qblk = gridDim.y - 1 - blockIdx.y;   // LPT
    const int bh = blockIdx.x;
    const int b = bh >> 4, h = bh & 15;
    const size_t base = ((size_t)b * SEQ) * D_MODEL + (size_t)h * HEAD_DIM;

    const uint32_t sQ = sb;
    const uint32_t sKV = sb + AQ * 128;

    {
        const __nv_bfloat16* q0 = Q16 + base + (size_t)qblk * AQ * D_MODEL;
        #pragma unroll
        for (int i = 0; i < 4; i++) {
            int u = i * 256 + tid;
            int r = u >> 3, c = u & 7;
            cp16(sQ + swz128(r * 128 + c * 16), q0 + (size_t)r * D_MODEL + c * 8);
        }
    }
    CP_COMMIT();

    const int nkt = 2 * qblk + 2;

    {
        const __nv_bfloat16* srcs[2] = {K16 + base, V16 + base};
        #pragma unroll
        for (int t = 0; t < 2; t++)
            #pragma unroll
            for (int i = 0; i < 2; i++) {
                int u = i * 256 + tid;
                int r = u >> 3, c = u & 7;
                cp16(sKV + t * 8192 + swz128(r * 128 + c * 16),
                     srcs[t] + (size_t)r * D_MODEL + c * 8);
            }
    }
    CP_COMMIT();
    CP_WAIT(1);
    __syncthreads();

    uint32_t qf[4][4];
    {
        const int ar = wid * 16 + (lane & 15);
        const int ab = ((lane >> 4) & 1) * 16;
        #pragma unroll
        for (int ks = 0; ks < 4; ks++)
            ldsm4(qf[ks], sQ + swz128((uint32_t)ar * 128 + ab + ks * 32));
    }

    float o[8][4];
    #pragma unroll
    for (int nt = 0; nt < 8; nt++)
        #pragma unroll
        for (int j = 0; j < 4; j++) o[nt][j] = 0.0f;
    float m0 = -1e30f, m1 = -1e30f, l0 = 0.0f, l1 = 0.0f;

    const int qr0 = qblk * AQ + wid * 16 + gid;
    const int row_min = qblk * AQ + wid * 16;
    const int row_max = row_min + 15;

    const int sbr = ((lane >> 4) & 1) * 8 + (lane & 7);
    const int sbb = ((lane >> 3) & 1) * 16;
    const int vrr = lane & 15;
    const int vbb = ((lane >> 4) & 1) * 16;

    const float SC = 0.125f * 1.44269504f / 256.0f;

    for (int kt = 0; kt < nkt; kt++) {
        const uint32_t st = sKV + (uint32_t)(kt & 1) * KV_STG;
        __syncthreads();
        if (kt + 1 < nkt) {
            const size_t koff = base + (size_t)(kt + 1) * 64 * D_MODEL;
            const __nv_bfloat16* srcs[2] = {K16 + koff, V16 + koff};
            const uint32_t dst = sKV + (uint32_t)((kt + 1) & 1) * KV_STG;
            #pragma unroll
            for (int t = 0; t < 2; t++)
                #pragma unroll
                for (int i = 0; i < 2; i++) {
                    int u = i * 256 + tid;
                    int r = u >> 3, c = u & 7;
                    cp16(dst + t * 8192 + swz128(r * 128 + c * 16),
                         srcs[t] + (size_t)r * D_MODEL + c * 8);
                }
            CP_COMMIT();
            CP_WAIT(1);
        } else {
            CP_WAIT(0);
        }
        __syncthreads();

        if (kt * 64 > row_max) continue;

        float s[8][4];
        #pragma unroll
        for (int nt = 0; nt < 8; nt++)
            #pragma unroll
            for (int j = 0; j < 4; j++) s[nt][j] = 0.0f;

        #pragma unroll
        for (int ks = 0; ks < 4; ks++) {
            #pragma unroll
            for (int np = 0; np < 4; np++) {
                uint32_t off = swz128((uint32_t)(np * 16 + sbr) * 128 + sbb + ks * 32);
                uint32_t rk[4];
                ldsm4(rk, st + off);
                mma_f16(s[2 * np],     qf[ks], rk[0], rk[1]);
                mma_f16(s[2 * np + 1], qf[ks], rk[2], rk[3]);
            }
        }

        const bool need_mask = (kt * 64 + 63 > row_min);
        #pragma unroll
        for (int nt = 0; nt < 8; nt++) {
            #pragma unroll
            for (int j = 0; j < 4; j++) s[nt][j] *= SC;
            if (need_mask) {
                const int kc = kt * 64 + nt * 8 + 2 * tig;
                if (kc     > qr0)     s[nt][0] = -1e30f;
                if (kc + 1 > qr0)     s[nt][1] = -1e30f;
                if (kc     > qr0 + 8) s[nt][2] = -1e30f;
                if (kc + 1 > qr0 + 8) s[nt][3] = -1e30f;
            }
        }

        float mx0 = -1e30f, mx1 = -1e30f;
        #pragma unroll
        for (int nt = 0; nt < 8; nt++) {
            mx0 = fmaxf(mx0, fmaxf(s[nt][0], s[nt][1]));
            mx1 = fmaxf(mx1, fmaxf(s[nt][2], s[nt][3]));
        }
        mx0 = fmaxf(mx0, __shfl_xor_sync(0xffffffffu, mx0, 1));
        mx0 = fmaxf(mx0, __shfl_xor_sync(0xffffffffu, mx0, 2));
        mx1 = fmaxf(mx1, __shfl_xor_sync(0xffffffffu, mx1, 1));
        mx1 = fmaxf(mx1, __shfl_xor_sync(0xffffffffu, mx1, 2));
        const float nm0 = fmaxf(m0, mx0), nm1 = fmaxf(m1, mx1);
        const float c0 = exp2f(m0 - nm0), c1 = exp2f(m1 - nm1);
        m0 = nm0; m1 = nm1;

        uint32_t pA[8], pB[8];
        float la0 = 0.0f, la1 = 0.0f;
        #pragma unroll
        for (int nt = 0; nt < 8; nt++) {
            float p0 = exp2f(s[nt][0] - m0), p1 = exp2f(s[nt][1] - m0);
            float p2 = exp2f(s[nt][2] - m1), p3 = exp2f(s[nt][3] - m1);
            la0 += p0 + p1; la1 += p2 + p3;
            pA[nt] = pack_f16x2(p0, p1);
            pB[nt] = pack_f16x2(p2, p3);
        }
        la0 += __shfl_xor_sync(0xffffffffu, la0, 1);
        la0 += __shfl_xor_sync(0xffffffffu, la0, 2);
        la1 += __shfl_xor_sync(0xffffffffu, la1, 1);
        la1 += __shfl_xor_sync(0xffffffffu, la1, 2);
        l0 = l0 * c0 + la0;
        l1 = l1 * c1 + la1;
        #pragma unroll
        for (int nt = 0; nt < 8; nt++) {
            o[nt][0] *= c0; o[nt][1] *= c0;
            o[nt][2] *= c1; o[nt][3] *= c1;
        }

        #pragma unroll
        for (int kk = 0; kk < 4; kk++) {
            uint32_t aH[4] = {pA[2 * kk], pB[2 * kk], pA[2 * kk + 1], pB[2 * kk + 1]};
            #pragma unroll
            for (int np = 0; np < 4; np++) {
                uint32_t off = swz128((uint32_t)(kk * 16 + vrr) * 128 + vbb + np * 32);
                uint32_t rv[4];
                ldsm4t(rv, st + 8192 + off);
                mma_f16(o[2 * np],     aH, rv[0], rv[1]);
                mma_f16(o[2 * np + 1], aH, rv[2], rv[3]);
            }
        }
    }

    const float i0 = 1.0f / l0, i1 = 1.0f / l1;
    const size_t r0a = base + (size_t)qr0 * D_MODEL;
    const size_t r1a = base + (size_t)(qr0 + 8) * D_MODEL;
    #pragma unroll
    for (int nt = 0; nt < 8; nt++) {
        const int col = nt * 8 + 2 * tig;
        *(uint32_t*)&Y16[r0a + col] = pack_f16x2(o[nt][0] * i0, o[nt][1] * i0);
        *(uint32_t*)&Y16[r1a + col] = pack_f16x2(o[nt][2] * i1, o[nt][3] * i1);
    }
}

// ---------------- launch ----------------
extern "C" void kernel_launch(void* const* d_in, const int* in_sizes, int n_in,
                              void* d_out, int out_size)
{
    const float* x  = (const float*)d_in[0];
    const float* Wq = (const float*)d_in[1];
    const float* bq = (const float*)d_in[2];
    const float* Wk = (const float*)d_in[3];
    const float* bk = (const float*)d_in[4];
    const float* Wv = (const float*)d_in[5];
    const float* bv = (const float*)d_in[6];
    const float* Wp = (const float*)d_in[7];
    const float* bp = (const float*)d_in[8];
    float* out = (float*)d_out;

    __nv_bfloat16 *q16, *k16, *v16, *y16, *x16, *w256;
    cudaGetSymbolAddress((void**)&q16, g_q16);
    cudaGetSymbolAddress((void**)&k16, g_k16);
    cudaGetSymbolAddress((void**)&v16, g_v16);
    cudaGetSymbolAddress((void**)&y16, g_y16);
    cudaGetSymbolAddress((void**)&x16, g_x16);
    cudaGetSymbolAddress((void**)&w256, g_w256);

    cudaFuncSetAttribute(gemm_hmma<1>,
                         cudaFuncAttributeMaxDynamicSharedMemorySize, GEMM_SMEM);
    cudaFuncSetAttribute(gemm_hmma<2>,
                         cudaFuncAttributeMaxDynamicSharedMemorySize, GEMM_SMEM);
    cudaFuncSetAttribute(attn_hmma,
                         cudaFuncAttributeMaxDynamicSharedMemorySize, ATT_SMEM);

    split_all<<<(XN4 + 4 * WN4) / 256, 256>>>(
        (const float4*)x, (const float4*)Wq, (const float4*)Wk,
        (const float4*)Wv, (const float4*)Wp,
        (uint32_t*)x16, (uint32_t*)w256);

    gemm_hmma<1><<<dim3(24, 32), 256, GEMM_SMEM>>>(
        x16, w256, bq, bk, bv,
        nullptr, q16, k16, v16);

    attn_hmma<<<dim3(BATCH * N_HEADS, SEQ / AQ), 256, ATT_SMEM>>>(
        q16, k16, v16, y16);

    gemm_hmma<2><<<dim3(8, 32), 256, GEMM_SMEM>>>(
        y16, w256 + 3u * WSZ, bp, nullptr, nullptr,
        out, nullptr, nullptr, nullptr);
}